// round 14
// baseline (speedup 1.0000x reference)
#include <cuda_runtime.h>
#include <cuda_bf16.h>
#include <cuda_fp16.h>
#include <mma.h>
#include <math.h>
#include <stdint.h>

using namespace nvcuda;

#define BATCH 16
#define INDIM 512
#define MIDC  256
#define HW    4096
#define HEADS 8

// ---------------- scratch (device globals; no allocation) ----------------
__device__ __half g_buf1h[BATCH*MIDC*HW];   // reduce-GEMM output (pre-dw), fp16
__device__ __half g_xr_h[BATCH*MIDC*HW];    // xr (post dw+BN+ReLU), fp16, spatial
__device__ float  g_means[BATCH*MIDC];
__device__ float  g_nrm  [BATCH*MIDC];
__device__ float  g_gram_part[BATCH*HEADS*8*1024];
__device__ float  g_attnW[BATCH*HEADS*1024];
__device__ __nv_bfloat16 g_fused_bf[BATCH*INDIM*HW]; // [attn_out | gated fwm]
__device__ __nv_bfloat16 g_wred    [MIDC*INDIM];
__device__ __nv_bfloat16 g_wpost   [INDIM*2*MIDC];

// ================= GEMM common =================
#define AS_STRIDE 40
#define BS_STRIDE 136
#define BF_STRIDE 132
#define CS_STRIDE 132
#define GEMM_SMEM (128*CS_STRIDE*4)
// reduce GEMM (M=256) smem: A 2*256*40*2 + Bf 2*32*132*4 + Bs 32*136*2
#define RED_SMEM (2*256*AS_STRIDE*2 + 2*32*BF_STRIDE*4 + 32*BS_STRIDE*2)

__device__ __forceinline__ void cp16(void* sdst, const void* gsrc) {
    uint32_t a = (uint32_t)__cvta_generic_to_shared(sdst);
    asm volatile("cp.async.cg.shared.global [%0], [%1], 16;\n" :: "r"(a), "l"(gsrc));
}
#define CP_COMMIT() asm volatile("cp.async.commit_group;\n" ::: "memory")
#define CP_WAIT(n)  asm volatile("cp.async.wait_group %0;\n" :: "n"(n) : "memory")

__device__ __forceinline__ void mma_step(
    const __nv_bfloat16* As, const __nv_bfloat16* Bs, int wm, int wn,
    wmma::fragment<wmma::accumulator, 16, 16, 16, float> acc[2][4]) {
#pragma unroll
    for (int ks = 0; ks < 2; ks++) {
        wmma::fragment<wmma::matrix_a, 16, 16, 16, __nv_bfloat16, wmma::row_major> af[2];
        wmma::fragment<wmma::matrix_b, 16, 16, 16, __nv_bfloat16, wmma::row_major> bf[4];
#pragma unroll
        for (int i = 0; i < 2; i++)
            wmma::load_matrix_sync(af[i], As + (wm*32 + i*16) * AS_STRIDE + ks*16, AS_STRIDE);
#pragma unroll
        for (int j = 0; j < 4; j++)
            wmma::load_matrix_sync(bf[j], Bs + (ks*16) * BS_STRIDE + wn*64 + j*16, BS_STRIDE);
#pragma unroll
        for (int i = 0; i < 2; i++)
#pragma unroll
            for (int j = 0; j < 4; j++)
                wmma::mma_sync(acc[i][j], af[i], bf[j], acc[i][j]);
    }
}

// ------- reduce GEMM: M=256 tile, 512 threads, fp32 act staged + smem convert ------
__global__ void __launch_bounds__(512)
k_gemm_red(const __nv_bfloat16* __restrict__ W,
           const float* __restrict__ act,
           const float* __restrict__ bias,
           __half* __restrict__ out) {
    extern __shared__ char sm[];
    __nv_bfloat16* As0 = (__nv_bfloat16*)sm;                         // 2 x 256*40
    float*         Bf0 = (float*)(sm + 2*256*AS_STRIDE*2);           // 2 x 32*132
    __nv_bfloat16* Bs  = (__nv_bfloat16*)(sm + 2*256*AS_STRIDE*2 + 2*32*BF_STRIDE*4);
    float*         Cs  = (float*)sm;                                 // 64*132 band

    int tid = threadIdx.x;
    int warp = tid >> 5;
    int wr = warp >> 2, wc = warp & 3;     // 4x4 warp grid: 64-row x 32-col tiles
    int nb = blockIdx.x * 128, b = blockIdx.z;

    const float* Bg = act + (size_t)b * 512 * 4096 + nb;

    int ar0 = tid >> 2,  ac0 = (tid & 3) * 8;     // A: 256x32, ids 0..1023 (2/thr)
    int br0 = tid >> 5,  bs0 = (tid & 31) * 4;    // Bf: 32x128 f32, ids 0..1023 (2/thr)

    wmma::fragment<wmma::accumulator, 16, 16, 16, float> acc[4][2];
#pragma unroll
    for (int i = 0; i < 4; i++)
#pragma unroll
        for (int j = 0; j < 2; j++) wmma::fill_fragment(acc[i][j], 0.0f);

    {
#pragma unroll
        for (int t = 0; t < 2; t++) {
            int id = tid + t*512;
            int r = id >> 2, c8 = (id & 3) * 8;
            cp16(As0 + r*AS_STRIDE + c8, W + (size_t)r*512 + c8);
        }
#pragma unroll
        for (int t = 0; t < 2; t++) {
            int id = tid + t*512;
            int r = id >> 5, cs = (id & 31) * 4;
            cp16(Bf0 + r*BF_STRIDE + cs, Bg + (size_t)r*4096 + cs);
        }
        CP_COMMIT();
    }

    for (int it = 0; it < 16; it++) {
        int cur = it & 1;
        if (it < 15) {
            int kc = (it + 1) * 32;
            __nv_bfloat16* As = As0 + (cur^1)*256*AS_STRIDE;
            float*         Bf = Bf0 + (cur^1)*32*BF_STRIDE;
#pragma unroll
            for (int t = 0; t < 2; t++) {
                int id = tid + t*512;
                int r = id >> 2, c8 = (id & 3) * 8;
                cp16(As + r*AS_STRIDE + c8, W + (size_t)r*512 + kc + c8);
            }
#pragma unroll
            for (int t = 0; t < 2; t++) {
                int id = tid + t*512;
                int r = id >> 5, cs = (id & 31) * 4;
                cp16(Bf + r*BF_STRIDE + cs, Bg + (size_t)(kc + r)*4096 + cs);
            }
            CP_COMMIT();
            CP_WAIT(1);
        } else {
            CP_WAIT(0);
        }
        __syncthreads();
        // convert Bf[cur] (32x128 f32) -> Bs bf16 : 2048 pairs / 512 thr
        const float* Bf = Bf0 + cur*32*BF_STRIDE;
#pragma unroll
        for (int t = 0; t < 4; t++) {
            int e2 = (tid + t*512) * 2;
            int r = e2 >> 7, c = e2 & 127;
            __nv_bfloat162 pk = __floats2bfloat162_rn(Bf[r*BF_STRIDE + c],
                                                      Bf[r*BF_STRIDE + c + 1]);
            *(uint32_t*)(Bs + r*BS_STRIDE + c) = *(uint32_t*)&pk;
        }
        __syncthreads();
        const __nv_bfloat16* As = As0 + cur*256*AS_STRIDE;
#pragma unroll
        for (int ks = 0; ks < 2; ks++) {
            wmma::fragment<wmma::matrix_a, 16, 16, 16, __nv_bfloat16, wmma::row_major> af[4];
            wmma::fragment<wmma::matrix_b, 16, 16, 16, __nv_bfloat16, wmma::row_major> bf[2];
#pragma unroll
            for (int i = 0; i < 4; i++)
                wmma::load_matrix_sync(af[i], As + (wr*64 + i*16) * AS_STRIDE + ks*16, AS_STRIDE);
#pragma unroll
            for (int j = 0; j < 2; j++)
                wmma::load_matrix_sync(bf[j], Bs + (ks*16) * BS_STRIDE + wc*32 + j*16, BS_STRIDE);
#pragma unroll
            for (int i = 0; i < 4; i++)
#pragma unroll
                for (int j = 0; j < 2; j++)
                    wmma::mma_sync(acc[i][j], af[i], bf[j], acc[i][j]);
        }
        __syncthreads();
    }
    // banded epilogue: 4 bands of 64 rows; Cs overlaps dead A/B buffers
#pragma unroll
    for (int band = 0; band < 4; band++) {
        if (wr == band) {
#pragma unroll
            for (int i = 0; i < 4; i++)
#pragma unroll
                for (int j = 0; j < 2; j++)
                    wmma::store_matrix_sync(Cs + (i*16)*CS_STRIDE + wc*32 + j*16,
                                            acc[i][j], CS_STRIDE, wmma::mem_row_major);
        }
        __syncthreads();
        // write 64x128 fp16: 4096 half2 / 512 thr = 8 each
#pragma unroll
        for (int t = 0; t < 8; t++) {
            int id = tid + t*512;
            int r = id >> 6, c2 = (id & 63) * 2;
            int gr = band*64 + r;
            float bi = bias[gr];
            __half2 h = __floats2half2_rn(Cs[r*CS_STRIDE + c2] + bi,
                                          Cs[r*CS_STRIDE + c2 + 1] + bi);
            size_t off = ((size_t)b * MIDC + gr) * 4096 + nb + c2;
            *(uint32_t*)(out + off) = *(uint32_t*)&h;
        }
        __syncthreads();
    }
}

// ---------------- post GEMM: bf16 act, cp.async 2-stage pipeline ----------------
__global__ void __launch_bounds__(256)
k_gemm_pipe(const __nv_bfloat16* __restrict__ W,
            const __nv_bfloat16* __restrict__ act,
            const float* __restrict__ bias,
            const float* __restrict__ resid,
            float* __restrict__ out,
            int Mtot) {
    extern __shared__ char sm[];
    __nv_bfloat16* As0 = (__nv_bfloat16*)sm;
    __nv_bfloat16* Bs0 = (__nv_bfloat16*)(sm + 2*128*AS_STRIDE*2);
    float*         Cs  = (float*)sm;

    int tid = threadIdx.x;
    int w   = tid >> 5;
    int wm  = w & 3;
    int wn  = w >> 2;
    int nb = blockIdx.x * 128, mb = blockIdx.y * 128, b = blockIdx.z;

    const __nv_bfloat16* Ag = W + (size_t)mb * 512;
    const __nv_bfloat16* Bg = act + (size_t)b * 512 * 4096 + nb;

    int ar0 = tid >> 2,  ac0 = (tid & 3) * 8;
    int br0 = tid >> 4,  bc0 = (tid & 15) * 8;

    wmma::fragment<wmma::accumulator, 16, 16, 16, float> acc[2][4];
#pragma unroll
    for (int i = 0; i < 2; i++)
#pragma unroll
        for (int j = 0; j < 4; j++) wmma::fill_fragment(acc[i][j], 0.0f);

    {
#pragma unroll
        for (int t = 0; t < 2; t++) {
            int r = ar0 + t*64;
            cp16(As0 + r*AS_STRIDE + ac0, Ag + (size_t)r*512 + ac0);
        }
#pragma unroll
        for (int t = 0; t < 2; t++) {
            int r = br0 + t*16;
            cp16(Bs0 + r*BS_STRIDE + bc0, Bg + (size_t)r*4096 + bc0);
        }
        CP_COMMIT();
    }

    for (int it = 0; it < 16; it++) {
        int cur = it & 1;
        if (it < 15) {
            int kc = (it + 1) * 32;
            __nv_bfloat16* As = As0 + (cur^1)*128*AS_STRIDE;
            __nv_bfloat16* Bs = Bs0 + (cur^1)*32*BS_STRIDE;
#pragma unroll
            for (int t = 0; t < 2; t++) {
                int r = ar0 + t*64;
                cp16(As + r*AS_STRIDE + ac0, Ag + (size_t)r*512 + kc + ac0);
            }
#pragma unroll
            for (int t = 0; t < 2; t++) {
                int r = br0 + t*16;
                cp16(Bs + r*BS_STRIDE + bc0, Bg + (size_t)(kc + r)*4096 + bc0);
            }
            CP_COMMIT();
            CP_WAIT(1);
        } else {
            CP_WAIT(0);
        }
        __syncthreads();
        mma_step(As0 + cur*128*AS_STRIDE, Bs0 + cur*32*BS_STRIDE, wm, wn, acc);
        __syncthreads();
    }
#pragma unroll
    for (int i = 0; i < 2; i++)
#pragma unroll
        for (int j = 0; j < 4; j++)
            wmma::store_matrix_sync(Cs + (wm*32 + i*16) * CS_STRIDE + wn*64 + j*16,
                                    acc[i][j], CS_STRIDE, wmma::mem_row_major);
    __syncthreads();
#pragma unroll
    for (int t = 0; t < 16; t++) {
        int id = tid + t * 256;
        int r = id >> 5, c = (id & 31) * 4;
        float bi = bias[mb + r];
        float4 v = *(float4*)(Cs + r * CS_STRIDE + c);
        v.x += bi; v.y += bi; v.z += bi; v.w += bi;
        size_t off = ((size_t)b * Mtot + mb + r) * 4096 + nb + c;
        float4 rr = *(const float4*)(resid + off);
        v.x += rr.x; v.y += rr.y; v.z += rr.z; v.w += rr.w;
        *(float4*)(out + off) = v;
    }
}

// ---------------- weight conversion ----------------
__global__ void __launch_bounds__(256) k_cvt(const float* __restrict__ src,
                                             __nv_bfloat16* __restrict__ dst, int n) {
    int i = (blockIdx.x * 256 + threadIdx.x) * 4;
    if (i < n) {
        float4 v = *(const float4*)(src + i);
        __nv_bfloat162 p0 = __floats2bfloat162_rn(v.x, v.y);
        __nv_bfloat162 p1 = __floats2bfloat162_rn(v.z, v.w);
        uint2 pk;
        pk.x = *(uint32_t*)&p0; pk.y = *(uint32_t*)&p1;
        *(uint2*)(dst + i) = pk;
    }
}

// ================= radix-8 FFT (64-pt, 2 stages/dim, 512 threads, 1 bfly/thr) ======
template<int Q, int M, bool INV>
__device__ __forceinline__ void fft8s(float* Ar, float* Ai,
                                      const float* twr, const float* twi,
                                      int tid, bool col) {
    const float S2 = 0.70710678118654752440f;
    int bf = tid;
    int line = bf & 63;
    int j8 = bf >> 6;
    int blk = j8 / Q, j = j8 - blk * Q;
    int base = blk * (8 * Q) + j;
    int idx[8];
#pragma unroll
    for (int r = 0; r < 8; r++) {
        int p = base + r * Q;
        idx[r] = col ? p*65 + line : line*65 + p;
    }
    float xr[8], xi[8];
#pragma unroll
    for (int r = 0; r < 8; r++) { xr[r] = Ar[idx[r]]; xi[r] = Ai[idx[r]]; }
    if (INV) {
#pragma unroll
        for (int r = 1; r < 8; r++) {
            float wr = twr[M*j*r], wi = twi[M*j*r];
            float a = xr[r], bb = xi[r];
            xr[r] = a*wr + bb*wi;
            xi[r] = bb*wr - a*wi;
        }
    }
    float t0r=xr[0]+xr[4], t0i=xi[0]+xi[4];
    float t1r=xr[0]-xr[4], t1i=xi[0]-xi[4];
    float t2r=xr[2]+xr[6], t2i=xi[2]+xi[6];
    float d2r=xr[2]-xr[6], d2i=xi[2]-xi[6];
    float t3r, t3i;
    if (INV) { t3r = -d2i; t3i =  d2r; } else { t3r =  d2i; t3i = -d2r; }
    float e0r=t0r+t2r, e0i=t0i+t2i;
    float e1r=t1r+t3r, e1i=t1i+t3i;
    float e2r=t0r-t2r, e2i=t0i-t2i;
    float e3r=t1r-t3r, e3i=t1i-t3i;
    float u0r=xr[1]+xr[5], u0i=xi[1]+xi[5];
    float u1r=xr[1]-xr[5], u1i=xi[1]-xi[5];
    float u2r=xr[3]+xr[7], u2i=xi[3]+xi[7];
    float v2r=xr[3]-xr[7], v2i=xi[3]-xi[7];
    float u3r, u3i;
    if (INV) { u3r = -v2i; u3i =  v2r; } else { u3r =  v2i; u3i = -v2r; }
    float o0r=u0r+u2r, o0i=u0i+u2i;
    float o1r=u1r+u3r, o1i=u1i+u3i;
    float o2r=u0r-u2r, o2i=u0i-u2i;
    float o3r=u1r-u3r, o3i=u1i-u3i;
    float w1i = INV ?  S2 : -S2;
    { float a=o1r, bb=o1i; o1r = S2*a - w1i*bb; o1i = S2*bb + w1i*a; }
    { float a=o2r, bb=o2i; if (INV) { o2r = -bb; o2i = a; } else { o2r = bb; o2i = -a; } }
    { float a=o3r, bb=o3i; o3r = -S2*a - w1i*bb; o3i = -S2*bb + w1i*a; }
    float yr[8], yi[8];
    yr[0]=e0r+o0r; yi[0]=e0i+o0i;
    yr[1]=e1r+o1r; yi[1]=e1i+o1i;
    yr[2]=e2r+o2r; yi[2]=e2i+o2i;
    yr[3]=e3r+o3r; yi[3]=e3i+o3i;
    yr[4]=e0r-o0r; yi[4]=e0i-o0i;
    yr[5]=e1r-o1r; yi[5]=e1i-o1i;
    yr[6]=e2r-o2r; yi[6]=e2i-o2i;
    yr[7]=e3r-o3r; yi[7]=e3i-o3i;
    if (!INV) {
#pragma unroll
        for (int r = 1; r < 8; r++) {
            float wr = twr[M*j*r], wi = twi[M*j*r];
            float a = yr[r], bb = yi[r];
            yr[r] = a*wr - bb*wi;
            yi[r] = a*wi + bb*wr;
        }
    }
#pragma unroll
    for (int r = 0; r < 8; r++) { Ar[idx[r]] = yr[r]; Ai[idx[r]] = yi[r]; }
}

__device__ __forceinline__ void fft8_fwd_dim(float* Ar, float* Ai,
                                             const float* twr, const float* twi,
                                             int tid, bool col) {
    fft8s<8,1,false>(Ar, Ai, twr, twi, tid, col); __syncthreads();
    fft8s<1,8,false>(Ar, Ai, twr, twi, tid, col); __syncthreads();
}
__device__ __forceinline__ void fft8_inv_dim(float* Ar, float* Ai,
                                             const float* twr, const float* twi,
                                             int tid, bool col) {
    fft8s<1,8,true>(Ar, Ai, twr, twi, tid, col); __syncthreads();
    fft8s<8,1,true>(Ar, Ai, twr, twi, tid, col); __syncthreads();
}

__device__ __forceinline__ void fft_load_tw64(float* twr, float* twi, int tid) {
    if (tid < 64) {
        float s, c;
        sincosf(-6.28318530717958647692f * (float)tid * (1.0f/64.0f), &s, &c);
        twr[tid] = c; twi[tid] = s;
    }
}

// ---------------- K2: dw 3x3 + BN + ReLU + stats, 2 px/thread ----------
__global__ void __launch_bounds__(256) k_dw(const float* __restrict__ dww,
                                            const float* __restrict__ dwb,
                                            const float* __restrict__ gamma,
                                            const float* __restrict__ beta,
                                            const float* __restrict__ mean,
                                            const float* __restrict__ var) {
    int plane = blockIdx.x;
    int c = plane & (MIDC-1);
    __shared__ float tile[66*66];
    __shared__ float rs[8], rq[8];
    const __half* src = g_buf1h + (size_t)plane*HW;
    int tid = threadIdx.x;
#pragma unroll
    for (int i = 0; i < 8; i++) {
        int e = tid + i*256;
        int p = e*2;
        int r = p >> 6, cc = p & 63;
        __half2 h = *(const __half2*)(src + p);
        float2 f = __half22float2(h);
        float* t = &tile[(r+1)*66 + cc + 1];
        t[0] = f.x; t[1] = f.y;
    }
    for (int i = tid; i < 260; i += 256) {
        int a;
        if (i < 66)       a = i;
        else if (i < 132) a = 65*66 + (i - 66);
        else if (i < 196) a = (i - 131)*66;
        else              a = (i - 195)*66 + 65;
        tile[a] = 0.f;
    }
    __syncthreads();
    float w0 = dww[c*9+0], w1 = dww[c*9+1], w2 = dww[c*9+2];
    float w3 = dww[c*9+3], w4 = dww[c*9+4], w5 = dww[c*9+5];
    float w6 = dww[c*9+6], w7 = dww[c*9+7], w8 = dww[c*9+8];
    float scale = gamma[c] * rsqrtf(var[c] + 1e-5f);
    float shift = beta[c] - mean[c]*scale;
    float bia = dwb[c];
    float s = 0.f, sq = 0.f;
    __half* dst = g_xr_h + (size_t)plane*HW;
#pragma unroll
    for (int i = 0; i < 8; i++) {
        int e = tid + i*256;
        int p = e*2;
        int py = p >> 6, px = p & 63;
        const float* t0 = &tile[py*66 + px];
        float r00=t0[0],  r01=t0[1],  r02=t0[2],  r03=t0[3];
        float r10=t0[66], r11=t0[67], r12=t0[68], r13=t0[69];
        float r20=t0[132],r21=t0[133],r22=t0[134],r23=t0[135];
        float a0 = r00*w0 + r01*w1 + r02*w2
                 + r10*w3 + r11*w4 + r12*w5
                 + r20*w6 + r21*w7 + r22*w8;
        float a1 = r01*w0 + r02*w1 + r03*w2
                 + r11*w3 + r12*w4 + r13*w5
                 + r21*w6 + r22*w7 + r23*w8;
        a0 = fmaxf((a0 + bia)*scale + shift, 0.f);
        a1 = fmaxf((a1 + bia)*scale + shift, 0.f);
        *(__half2*)(dst + p) = __floats2half2_rn(a0, a1);
        s += a0 + a1; sq += a0*a0 + a1*a1;
    }
#pragma unroll
    for (int o = 16; o; o >>= 1) {
        s  += __shfl_xor_sync(0xffffffffu, s,  o);
        sq += __shfl_xor_sync(0xffffffffu, sq, o);
    }
    int wid = tid >> 5;
    if ((tid & 31) == 0) { rs[wid] = s; rq[wid] = sq; }
    __syncthreads();
    if (tid == 0) {
        float ts = 0.f, tq = 0.f;
#pragma unroll
        for (int w = 0; w < 8; w++) { ts += rs[w]; tq += rq[w]; }
        g_means[plane] = ts * (1.f/4096.f);
        g_nrm[plane]   = sqrtf(tq);   // Parseval
    }
}

// ---- K7: packed-real fwm + inline SE gate, 2 planes/CTA, radix-8, 512 threads ----
__global__ void __launch_bounds__(512) k_fwm2(const float* __restrict__ gw1,
                                              const float* __restrict__ gb1,
                                              const float* __restrict__ gw2,
                                              const float* __restrict__ gb2) {
    __shared__ float Ar[64*65], Ai[64*65], twr[64], twi[64];
    __shared__ int mate[64];
    __shared__ float smn[MIDC], sh[32], sgate[2];
    int pp = blockIdx.x;
    int plane0 = pp * 2;
    int b = plane0 >> 8, c0 = plane0 & (MIDC-1);
    int tid = threadIdx.x;
    const __half* x0 = g_xr_h + (size_t)plane0*HW;
    const __half* x1 = x0 + HW;
#pragma unroll
    for (int i = 0; i < 8; i++) {
        int p = tid + i*512; int r = p >> 6, cc = p & 63;
        Ar[r*65+cc] = __half2float(x0[p]);
        Ai[r*65+cc] = __half2float(x1[p]);
    }
    fft_load_tw64(twr, twi, tid);
    if (tid < 64) {
        int rv = ((tid & 7) << 3) | (tid >> 3);
        int nk = (64 - rv) & 63;
        mate[tid] = ((nk & 7) << 3) | (nk >> 3);
    }
    if (tid >= 64 && tid < 64 + MIDC) smn[tid - 64] = g_means[b*MIDC + tid - 64];
    __syncthreads();
    // inline SE gate: layer 1 on threads < 256 (8 threads per output)
    if (tid < 256) {
        int o = tid >> 3, part = tid & 7;
        const float* wr = gw1 + o*MIDC + part*32;
        const float* mr = smn + part*32;
        float a = 0.f;
#pragma unroll
        for (int j = 0; j < 32; j++) a += wr[j]*mr[j];
#pragma unroll
        for (int off = 4; off; off >>= 1)
            a += __shfl_down_sync(0xffffffffu, a, off, 8);
        if (part == 0) sh[o] = fmaxf(a + gb1[o], 0.f);
    }
    __syncthreads();
    if (tid < 2) {
        int ch = c0 + tid;
        float a = gb2[ch];
        const float* wr = gw2 + ch*32;
#pragma unroll
        for (int j = 0; j < 32; j++) a += wr[j]*sh[j];
        sgate[tid] = 1.f / (1.f + expf(-a));
    }
    // (no explicit sync needed: FFT stages below all end in __syncthreads)
    fft8_fwd_dim(Ar, Ai, twr, twi, tid, false);
    fft8_fwd_dim(Ar, Ai, twr, twi, tid, true);
#pragma unroll
    for (int i = 0; i < 8; i++) {
        int p = tid + i*512; int r = p >> 6, cc = p & 63;
        int mr = mate[r], mc = mate[cc];
        int fm = mr*64 + mc;
        if (p <= fm) {
            int a  = r*65 + cc;
            int am = mr*65 + mc;
            float zpr = Ar[a],  zpi = Ai[a];
            float zmr = Ar[am], zmi = Ai[am];
            float f1r = 0.5f*(zpr + zmr), f1i = 0.5f*(zpi - zmi);
            float f2r = 0.5f*(zpi + zmi), f2i = 0.5f*(zmr - zpr);
            float W1r = f1r*f1r - f1i*f1i, W1i = 2.f*f1r*f1i;
            float W2r = f2r*f2r - f2i*f2i, W2i = 2.f*f2r*f2i;
            Ar[a]  = W1r - W2i;  Ai[a]  = W1i + W2r;
            Ar[am] = W1r + W2i;  Ai[am] = W2r - W1i;
        }
    }
    __syncthreads();
    fft8_inv_dim(Ar, Ai, twr, twi, tid, false);
    fft8_inv_dim(Ar, Ai, twr, twi, tid, true);
    float sc0 = sgate[0] * (1.f/262144.f);
    float sc1 = sgate[1] * (1.f/262144.f);
    __nv_bfloat16* dst0 = g_fused_bf + ((size_t)b*INDIM + MIDC + c0)*HW;
    __nv_bfloat16* dst1 = dst0 + HW;
#pragma unroll
    for (int i = 0; i < 8; i++) {
        int p = tid + i*512; int r = p >> 6, cc = p & 63;
        int a = r*65 + cc;
        dst0[p] = __float2bfloat16(Ar[a] * sc0);
        dst1[p] = __float2bfloat16(Ai[a] * sc1);
    }
}

// ------- K4a: spatial Gram via wmma: C[32,32] = X[32,512] * Y^T ---
#define GX_STRIDE 72
__global__ void __launch_bounds__(256) k_gram() {
    int sl = blockIdx.x, h = blockIdx.y, b = blockIdx.z;
    size_t base = ((size_t)b*MIDC + h*32) * HW;
    __shared__ __align__(16) __half sX[32*GX_STRIDE];
    __shared__ __align__(16) __half sY[32*GX_STRIDE];
    __shared__ float sC[8][256];
    int tid = threadIdx.x;
    int warp = tid >> 5;
    int tile = warp & 3;
    int kgrp = warp >> 2;
    int ti = tile >> 1, tj = tile & 1;

    wmma::fragment<wmma::accumulator, 16, 16, 16, float> acc;
    wmma::fill_fragment(acc, 0.0f);

    for (int it = 0; it < 8; it++) {
        int o = sl*512 + it*64;
        int row = o >> 6;
        int grow = (64 - row) & 63;
        __syncthreads();
        for (int idx = tid; idx < 1024; idx += 256) {
            int cc = idx >> 5, nn = (idx & 31) * 2;
            __half2 hx = *(const __half2*)(&g_xr_h[base + (size_t)cc*HW + o + nn]);
            sX[cc*GX_STRIDE + nn]     = __low2half(hx);
            sX[cc*GX_STRIDE + nn + 1] = __high2half(hx);
            __half2 hy = *(const __half2*)(&g_xr_h[base + (size_t)cc*HW + grow*64 + nn]);
            sY[cc*GX_STRIDE + ((64 - nn) & 63)] = __low2half(hy);
            sY[cc*GX_STRIDE + 63 - nn]          = __high2half(hy);
        }
        __syncthreads();
        if ((it & 1) == kgrp) {
#pragma unroll
            for (int ks = 0; ks < 4; ks++) {
                wmma::fragment<wmma::matrix_a, 16, 16, 16, __half, wmma::row_major> af;
                wmma::fragment<wmma::matrix_b, 16, 16, 16, __half, wmma::col_major> bf;
                wmma::load_matrix_sync(af, sX + (ti*16)*GX_STRIDE + ks*16, GX_STRIDE);
                wmma::load_matrix_sync(bf, sY + (tj*16)*GX_STRIDE + ks*16, GX_STRIDE);
                wmma::mma_sync(acc, af, bf, acc);
            }
        }
    }
    __syncthreads();
    wmma::store_matrix_sync(sC[warp], acc, 16, wmma::mem_row_major);
    __syncthreads();
    float* part = g_gram_part + ((size_t)(b*HEADS + h)*8 + sl)*1024;
    for (int e = tid; e < 1024; e += 256) {
        int c = e >> 5, d = e & 31;
        int t = (c >> 4)*2 + (d >> 4);
        int lr = c & 15, lc = d & 15;
        part[e] = sC[t][lr*16 + lc] + sC[t+4][lr*16 + lc];
    }
}

// ---------------- K4b: reduce partials + normalize + softmax ----------------
__global__ void __launch_bounds__(256) k_soft(const float* __restrict__ temp) {
    int h = blockIdx.x, b = blockIdx.y;
    __shared__ float sA[32][33], sN[32];
    int tid = threadIdx.x;
    if (tid < 32) sN[tid] = fmaxf(g_nrm[b*MIDC + h*32 + tid], 1e-12f);
    __syncthreads();
    float tK = temp[h];
    const float* part = g_gram_part + (size_t)(b*HEADS + h)*8*1024;
#pragma unroll
    for (int q = 0; q < 4; q++) {
        int e = tid*4 + q;
        int c = e >> 5, d = e & 31;
        float v = 0.f;
#pragma unroll
        for (int s = 0; s < 8; s++) v += part[s*1024 + e];
        sA[c][d] = v * tK / (sN[c] * sN[d]);
    }
    __syncthreads();
    int lane = tid & 31;
    float* aw = g_attnW + (size_t)(b*HEADS + h)*1024;
#pragma unroll
    for (int rr = 0; rr < 4; rr++) {
        int row = (tid >> 5)*4 + rr;
        float v = sA[row][lane];
        float mx = v;
#pragma unroll
        for (int o = 16; o; o >>= 1) mx = fmaxf(mx, __shfl_xor_sync(0xffffffffu, mx, o));
        float e = expf(v - mx);
        float smv = e;
#pragma unroll
        for (int o = 16; o; o >>= 1) smv += __shfl_xor_sync(0xffffffffu, smv, o);
        aw[row*32 + lane] = e / smv;
    }
}

// ---- K4c: spatial mix via wmma: out[32,64] = A[32,32] * S[32,64] per chunk ----
#define MS_STRIDE 72
#define MA_STRIDE 40
#define MC_STRIDE 68
__global__ void __launch_bounds__(256) k_mix() {
    int sl = blockIdx.x, h = blockIdx.y, b = blockIdx.z;
    size_t base = ((size_t)b*MIDC + h*32) * HW;
    __shared__ __align__(16) __half sA[32*MA_STRIDE];
    __shared__ __align__(16) __half sS[32*MS_STRIDE];
    __shared__ float sC[32*MC_STRIDE];
    int tid = threadIdx.x;
    const float* aw = g_attnW + (size_t)(b*HEADS + h)*1024;
#pragma unroll
    for (int q = 0; q < 4; q++) {
        int e = tid*4 + q;
        sA[(e >> 5)*MA_STRIDE + (e & 31)] = __float2half(aw[e]);
    }
    int warp = tid >> 5;
    int ti = warp >> 2, tj = warp & 3;
    size_t fb2 = ((size_t)b*INDIM + h*32) * HW;
    for (int it = 0; it < 8; it++) {
        int o = sl*512 + it*64;
        int row = o >> 6;
        int grow = (64 - row) & 63;
        __syncthreads();
        for (int idx = tid; idx < 1024; idx += 256) {
            int cc = idx >> 5, nn = (idx & 31) * 2;
            float2 ff = __half22float2(*(const __half2*)(&g_xr_h[base + (size_t)cc*HW + o + nn]));
            const __half* rv = &g_xr_h[base + (size_t)cc*HW + grow*64];
            float r0 = __half2float(rv[(64 - nn) & 63]);
            float r1 = __half2float(rv[63 - nn]);
            *(__half2*)(&sS[cc*MS_STRIDE + nn]) =
                __floats2half2_rn(0.5f*(ff.x + r0), 0.5f*(ff.y + r1));
        }
        __syncthreads();
        {
            wmma::fragment<wmma::accumulator, 16, 16, 16, float> acc;
            wmma::fill_fragment(acc, 0.0f);
#pragma unroll
            for (int ks = 0; ks < 2; ks++) {
                wmma::fragment<wmma::matrix_a, 16, 16, 16, __half, wmma::row_major> af;
                wmma::fragment<wmma::matrix_b, 16, 16, 16, __half, wmma::row_major> bf;
                wmma::load_matrix_sync(af, sA + (ti*16)*MA_STRIDE + ks*16, MA_STRIDE);
                wmma::load_matrix_sync(bf, sS + (ks*16)*MS_STRIDE + tj*16, MS_STRIDE);
                wmma::mma_sync(acc, af, bf, acc);
            }
            wmma::store_matrix_sync(sC + (ti*16)*MC_STRIDE + tj*16, acc,
                                    MC_STRIDE, wmma::mem_row_major);
        }
        __syncthreads();
        for (int idx = tid; idx < 1024; idx += 256) {
            int cc = idx >> 5, nn = (idx & 31) * 2;
            __nv_bfloat162 q = __floats2bfloat162_rn(sC[cc*MC_STRIDE + nn],
                                                     sC[cc*MC_STRIDE + nn + 1]);
            *(uint32_t*)(&g_fused_bf[fb2 + (size_t)cc*HW + o + nn]) = *(uint32_t*)&q;
        }
    }
}

// ---------------- launch ----------------
extern "C" void kernel_launch(void* const* d_in, const int* in_sizes, int n_in,
                              void* d_out, int out_size) {
    (void)in_sizes; (void)n_in; (void)out_size;
    const float* x        = (const float*)d_in[0];
    const float* reduce_w = (const float*)d_in[1];
    const float* reduce_b = (const float*)d_in[2];
    const float* dw_w     = (const float*)d_in[3];
    const float* dw_b     = (const float*)d_in[4];
    const float* bn_gamma = (const float*)d_in[5];
    const float* bn_beta  = (const float*)d_in[6];
    const float* bn_mean  = (const float*)d_in[7];
    const float* bn_var   = (const float*)d_in[8];
    const float* gate_w1  = (const float*)d_in[9];
    const float* gate_b1  = (const float*)d_in[10];
    const float* gate_w2  = (const float*)d_in[11];
    const float* gate_b2  = (const float*)d_in[12];
    const float* temp     = (const float*)d_in[13];
    const float* post_w   = (const float*)d_in[14];
    const float* post_b   = (const float*)d_in[15];
    float* out = (float*)d_out;

    cudaFuncSetAttribute((const void*)k_gemm_red,
                         cudaFuncAttributeMaxDynamicSharedMemorySize, RED_SMEM);
    cudaFuncSetAttribute((const void*)k_gemm_pipe,
                         cudaFuncAttributeMaxDynamicSharedMemorySize, GEMM_SMEM);

    __nv_bfloat16 *p_fbf, *p_wred, *p_wpost;
    cudaGetSymbolAddress((void**)&p_fbf,   g_fused_bf);
    cudaGetSymbolAddress((void**)&p_wred,  g_wred);
    cudaGetSymbolAddress((void**)&p_wpost, g_wpost);
    __half* p_buf1h;
    cudaGetSymbolAddress((void**)&p_buf1h, g_buf1h);

    cudaStream_t s2;
    cudaStreamCreateWithFlags(&s2, cudaStreamNonBlocking);
    cudaEvent_t e0, e1, e2;
    cudaEventCreateWithFlags(&e0, cudaEventDisableTiming);
    cudaEventCreateWithFlags(&e1, cudaEventDisableTiming);
    cudaEventCreateWithFlags(&e2, cudaEventDisableTiming);

    // fork side stream at entry
    cudaEventRecord(e0, 0);
    cudaStreamWaitEvent(s2, e0, 0);

    // side: post-weight conversion (only needed by gemm_pipe)
    k_cvt<<<(INDIM*2*MIDC/4 + 255)/256, 256, 0, s2>>>(post_w, p_wpost, INDIM*2*MIDC);

    // main: reduce-weight conversion -> reduce GEMM (M=256) -> dw
    k_cvt<<<(MIDC*INDIM/4 + 255)/256, 256>>>(reduce_w, p_wred, MIDC*INDIM);
    k_gemm_red<<<dim3(32, 1, BATCH), 512, RED_SMEM>>>(p_wred, x, reduce_b, p_buf1h);
    k_dw<<<BATCH*MIDC, 256>>>(dw_w, dw_b, bn_gamma, bn_beta, bn_mean, bn_var);

    // fork after dw: branch A (fwm2, gate inlined) on side stream
    cudaEventRecord(e1, 0);
    cudaStreamWaitEvent(s2, e1, 0);
    k_fwm2<<<BATCH*MIDC/2, 512, 0, s2>>>(gate_w1, gate_b1, gate_w2, gate_b2);

    // branch B (gram -> soft -> mix) on main
    k_gram<<<dim3(8, HEADS, BATCH), 256>>>();
    k_soft<<<dim3(HEADS, BATCH), 256>>>(temp);
    k_mix<<<dim3(8, HEADS, BATCH), 256>>>();

    // join: post GEMM needs both halves of fused + wpost
    cudaEventRecord(e2, s2);
    cudaStreamWaitEvent(0, e2, 0);
    k_gemm_pipe<<<dim3(32, 4, BATCH), 256, GEMM_SMEM>>>(
        p_wpost, p_fbf, post_b, x, out, INDIM);
}

// round 15
// speedup vs baseline: 1.0164x; 1.0164x over previous
#include <cuda_runtime.h>
#include <cuda_bf16.h>
#include <cuda_fp16.h>
#include <mma.h>
#include <math.h>
#include <stdint.h>

using namespace nvcuda;

#define BATCH 16
#define INDIM 512
#define MIDC  256
#define HW    4096
#define HEADS 8

// ---------------- scratch (device globals; no allocation) ----------------
__device__ __half g_buf1h[BATCH*MIDC*HW];   // reduce-GEMM output (pre-dw), fp16
__device__ __half g_xr_h[BATCH*MIDC*HW];    // xr (post dw+BN+ReLU), fp16, spatial
__device__ float  g_means[BATCH*MIDC];
__device__ float  g_nrm  [BATCH*MIDC];
__device__ float  g_gram_part[BATCH*HEADS*8*1024];
__device__ float  g_attnW[BATCH*HEADS*1024];
__device__ __nv_bfloat16 g_fused_bf[BATCH*INDIM*HW]; // [attn_out | gated fwm]
__device__ __nv_bfloat16 g_wred    [MIDC*INDIM];
__device__ __nv_bfloat16 g_wpost   [INDIM*2*MIDC];

// ================= GEMM common =================
#define AS_STRIDE 40
#define BS_STRIDE 136
#define BF_STRIDE 132
#define CS_STRIDE 132
#define GEMM_SMEM (128*CS_STRIDE*4)

__device__ __forceinline__ void cp16(void* sdst, const void* gsrc) {
    uint32_t a = (uint32_t)__cvta_generic_to_shared(sdst);
    asm volatile("cp.async.cg.shared.global [%0], [%1], 16;\n" :: "r"(a), "l"(gsrc));
}
#define CP_COMMIT() asm volatile("cp.async.commit_group;\n" ::: "memory")
#define CP_WAIT(n)  asm volatile("cp.async.wait_group %0;\n" :: "n"(n) : "memory")

__device__ __forceinline__ void mma_step(
    const __nv_bfloat16* As, const __nv_bfloat16* Bs, int wm, int wn,
    wmma::fragment<wmma::accumulator, 16, 16, 16, float> acc[2][4]) {
#pragma unroll
    for (int ks = 0; ks < 2; ks++) {
        wmma::fragment<wmma::matrix_a, 16, 16, 16, __nv_bfloat16, wmma::row_major> af[2];
        wmma::fragment<wmma::matrix_b, 16, 16, 16, __nv_bfloat16, wmma::row_major> bf[4];
#pragma unroll
        for (int i = 0; i < 2; i++)
            wmma::load_matrix_sync(af[i], As + (wm*32 + i*16) * AS_STRIDE + ks*16, AS_STRIDE);
#pragma unroll
        for (int j = 0; j < 4; j++)
            wmma::load_matrix_sync(bf[j], Bs + (ks*16) * BS_STRIDE + wn*64 + j*16, BS_STRIDE);
#pragma unroll
        for (int i = 0; i < 2; i++)
#pragma unroll
            for (int j = 0; j < 4; j++)
                wmma::mma_sync(acc[i][j], af[i], bf[j], acc[i][j]);
    }
}

// ---------------- reduce GEMM: fp32 act, cp.async-staged + smem convert (M=128) ----
__global__ void __launch_bounds__(256)
k_gemm_red(const __nv_bfloat16* __restrict__ W,
           const float* __restrict__ act,
           const float* __restrict__ bias,
           __half* __restrict__ out,
           int Mtot) {
    extern __shared__ char sm[];
    __nv_bfloat16* As0 = (__nv_bfloat16*)sm;
    float*         Bf0 = (float*)(sm + 2*128*AS_STRIDE*2);
    __nv_bfloat16* Bs  = (__nv_bfloat16*)(sm + 2*128*AS_STRIDE*2 + 2*32*BF_STRIDE*4);
    float*         Cs  = (float*)sm;

    int tid = threadIdx.x;
    int w   = tid >> 5;
    int wm  = w & 3;
    int wn  = w >> 2;
    int nb = blockIdx.x * 128, mb = blockIdx.y * 128, b = blockIdx.z;

    const __nv_bfloat16* Ag = W + (size_t)mb * 512;
    const float* Bg = act + (size_t)b * 512 * 4096 + nb;

    int ar0 = tid >> 2,  ac0 = (tid & 3) * 8;
    int br0 = tid >> 5,  bs0 = (tid & 31) * 4;

    wmma::fragment<wmma::accumulator, 16, 16, 16, float> acc[2][4];
#pragma unroll
    for (int i = 0; i < 2; i++)
#pragma unroll
        for (int j = 0; j < 4; j++) wmma::fill_fragment(acc[i][j], 0.0f);

    {
#pragma unroll
        for (int t = 0; t < 2; t++) {
            int r = ar0 + t*64;
            cp16(As0 + r*AS_STRIDE + ac0, Ag + (size_t)r*512 + ac0);
        }
#pragma unroll
        for (int t = 0; t < 4; t++) {
            int r = br0 + t*8;
            cp16(Bf0 + r*BF_STRIDE + bs0, Bg + (size_t)r*4096 + bs0);
        }
        CP_COMMIT();
    }

    for (int it = 0; it < 16; it++) {
        int cur = it & 1;
        if (it < 15) {
            int kc = (it + 1) * 32;
            __nv_bfloat16* As = As0 + (cur^1)*128*AS_STRIDE;
            float*         Bf = Bf0 + (cur^1)*32*BF_STRIDE;
#pragma unroll
            for (int t = 0; t < 2; t++) {
                int r = ar0 + t*64;
                cp16(As + r*AS_STRIDE + ac0, Ag + (size_t)r*512 + kc + ac0);
            }
#pragma unroll
            for (int t = 0; t < 4; t++) {
                int r = br0 + t*8;
                cp16(Bf + r*BF_STRIDE + bs0, Bg + (size_t)(kc + r)*4096 + bs0);
            }
            CP_COMMIT();
            CP_WAIT(1);
        } else {
            CP_WAIT(0);
        }
        __syncthreads();
        const float* Bf = Bf0 + cur*32*BF_STRIDE;
#pragma unroll
        for (int t = 0; t < 8; t++) {
            int e2 = (tid + t*256) * 2;
            int r = e2 >> 7, c = e2 & 127;
            __nv_bfloat162 pk = __floats2bfloat162_rn(Bf[r*BF_STRIDE + c],
                                                      Bf[r*BF_STRIDE + c + 1]);
            *(uint32_t*)(Bs + r*BS_STRIDE + c) = *(uint32_t*)&pk;
        }
        __syncthreads();
        mma_step(As0 + cur*128*AS_STRIDE, Bs, wm, wn, acc);
        __syncthreads();
    }
#pragma unroll
    for (int i = 0; i < 2; i++)
#pragma unroll
        for (int j = 0; j < 4; j++)
            wmma::store_matrix_sync(Cs + (wm*32 + i*16) * CS_STRIDE + wn*64 + j*16,
                                    acc[i][j], CS_STRIDE, wmma::mem_row_major);
    __syncthreads();
#pragma unroll
    for (int t = 0; t < 16; t++) {
        int id = tid + t * 256;
        int r = id >> 5, c = (id & 31) * 4;
        float bi = bias[mb + r];
        float4 v = *(float4*)(Cs + r * CS_STRIDE + c);
        __half2 h0 = __floats2half2_rn(v.x + bi, v.y + bi);
        __half2 h1 = __floats2half2_rn(v.z + bi, v.w + bi);
        uint2 pk; pk.x = *(uint32_t*)&h0; pk.y = *(uint32_t*)&h1;
        size_t off = ((size_t)b * Mtot + mb + r) * 4096 + nb + c;
        *(uint2*)(out + off) = pk;
    }
}

// ---------------- post GEMM: bf16 act, cp.async 2-stage pipeline ----------------
__global__ void __launch_bounds__(256)
k_gemm_pipe(const __nv_bfloat16* __restrict__ W,
            const __nv_bfloat16* __restrict__ act,
            const float* __restrict__ bias,
            const float* __restrict__ resid,
            float* __restrict__ out,
            int Mtot) {
    extern __shared__ char sm[];
    __nv_bfloat16* As0 = (__nv_bfloat16*)sm;
    __nv_bfloat16* Bs0 = (__nv_bfloat16*)(sm + 2*128*AS_STRIDE*2);
    float*         Cs  = (float*)sm;

    int tid = threadIdx.x;
    int w   = tid >> 5;
    int wm  = w & 3;
    int wn  = w >> 2;
    int nb = blockIdx.x * 128, mb = blockIdx.y * 128, b = blockIdx.z;

    const __nv_bfloat16* Ag = W + (size_t)mb * 512;
    const __nv_bfloat16* Bg = act + (size_t)b * 512 * 4096 + nb;

    int ar0 = tid >> 2,  ac0 = (tid & 3) * 8;
    int br0 = tid >> 4,  bc0 = (tid & 15) * 8;

    wmma::fragment<wmma::accumulator, 16, 16, 16, float> acc[2][4];
#pragma unroll
    for (int i = 0; i < 2; i++)
#pragma unroll
        for (int j = 0; j < 4; j++) wmma::fill_fragment(acc[i][j], 0.0f);

    {
#pragma unroll
        for (int t = 0; t < 2; t++) {
            int r = ar0 + t*64;
            cp16(As0 + r*AS_STRIDE + ac0, Ag + (size_t)r*512 + ac0);
        }
#pragma unroll
        for (int t = 0; t < 2; t++) {
            int r = br0 + t*16;
            cp16(Bs0 + r*BS_STRIDE + bc0, Bg + (size_t)r*4096 + bc0);
        }
        CP_COMMIT();
    }

    for (int it = 0; it < 16; it++) {
        int cur = it & 1;
        if (it < 15) {
            int kc = (it + 1) * 32;
            __nv_bfloat16* As = As0 + (cur^1)*128*AS_STRIDE;
            __nv_bfloat16* Bs = Bs0 + (cur^1)*32*BS_STRIDE;
#pragma unroll
            for (int t = 0; t < 2; t++) {
                int r = ar0 + t*64;
                cp16(As + r*AS_STRIDE + ac0, Ag + (size_t)r*512 + kc + ac0);
            }
#pragma unroll
            for (int t = 0; t < 2; t++) {
                int r = br0 + t*16;
                cp16(Bs + r*BS_STRIDE + bc0, Bg + (size_t)(kc + r)*4096 + bc0);
            }
            CP_COMMIT();
            CP_WAIT(1);
        } else {
            CP_WAIT(0);
        }
        __syncthreads();
        mma_step(As0 + cur*128*AS_STRIDE, Bs0 + cur*32*BS_STRIDE, wm, wn, acc);
        __syncthreads();
    }
#pragma unroll
    for (int i = 0; i < 2; i++)
#pragma unroll
        for (int j = 0; j < 4; j++)
            wmma::store_matrix_sync(Cs + (wm*32 + i*16) * CS_STRIDE + wn*64 + j*16,
                                    acc[i][j], CS_STRIDE, wmma::mem_row_major);
    __syncthreads();
#pragma unroll
    for (int t = 0; t < 16; t++) {
        int id = tid + t * 256;
        int r = id >> 5, c = (id & 31) * 4;
        float bi = bias[mb + r];
        float4 v = *(float4*)(Cs + r * CS_STRIDE + c);
        v.x += bi; v.y += bi; v.z += bi; v.w += bi;
        size_t off = ((size_t)b * Mtot + mb + r) * 4096 + nb + c;
        float4 rr = *(const float4*)(resid + off);
        v.x += rr.x; v.y += rr.y; v.z += rr.z; v.w += rr.w;
        *(float4*)(out + off) = v;
    }
}

// ---------------- weight conversion ----------------
__global__ void __launch_bounds__(256) k_cvt(const float* __restrict__ src,
                                             __nv_bfloat16* __restrict__ dst, int n) {
    int i = (blockIdx.x * 256 + threadIdx.x) * 4;
    if (i < n) {
        float4 v = *(const float4*)(src + i);
        __nv_bfloat162 p0 = __floats2bfloat162_rn(v.x, v.y);
        __nv_bfloat162 p1 = __floats2bfloat162_rn(v.z, v.w);
        uint2 pk;
        pk.x = *(uint32_t*)&p0; pk.y = *(uint32_t*)&p1;
        *(uint2*)(dst + i) = pk;
    }
}

// ================= radix-8 FFT (64-pt, 2 stages/dim, 512 threads, 1 bfly/thr) ======
template<int Q, int M, bool INV>
__device__ __forceinline__ void fft8s(float* Ar, float* Ai,
                                      const float* twr, const float* twi,
                                      int tid, bool col) {
    const float S2 = 0.70710678118654752440f;
    int bf = tid;
    int line = bf & 63;
    int j8 = bf >> 6;
    int blk = j8 / Q, j = j8 - blk * Q;
    int base = blk * (8 * Q) + j;
    int idx[8];
#pragma unroll
    for (int r = 0; r < 8; r++) {
        int p = base + r * Q;
        idx[r] = col ? p*65 + line : line*65 + p;
    }
    float xr[8], xi[8];
#pragma unroll
    for (int r = 0; r < 8; r++) { xr[r] = Ar[idx[r]]; xi[r] = Ai[idx[r]]; }
    if (INV) {
#pragma unroll
        for (int r = 1; r < 8; r++) {
            float wr = twr[M*j*r], wi = twi[M*j*r];
            float a = xr[r], bb = xi[r];
            xr[r] = a*wr + bb*wi;
            xi[r] = bb*wr - a*wi;
        }
    }
    float t0r=xr[0]+xr[4], t0i=xi[0]+xi[4];
    float t1r=xr[0]-xr[4], t1i=xi[0]-xi[4];
    float t2r=xr[2]+xr[6], t2i=xi[2]+xi[6];
    float d2r=xr[2]-xr[6], d2i=xi[2]-xi[6];
    float t3r, t3i;
    if (INV) { t3r = -d2i; t3i =  d2r; } else { t3r =  d2i; t3i = -d2r; }
    float e0r=t0r+t2r, e0i=t0i+t2i;
    float e1r=t1r+t3r, e1i=t1i+t3i;
    float e2r=t0r-t2r, e2i=t0i-t2i;
    float e3r=t1r-t3r, e3i=t1i-t3i;
    float u0r=xr[1]+xr[5], u0i=xi[1]+xi[5];
    float u1r=xr[1]-xr[5], u1i=xi[1]-xi[5];
    float u2r=xr[3]+xr[7], u2i=xi[3]+xi[7];
    float v2r=xr[3]-xr[7], v2i=xi[3]-xi[7];
    float u3r, u3i;
    if (INV) { u3r = -v2i; u3i =  v2r; } else { u3r =  v2i; u3i = -v2r; }
    float o0r=u0r+u2r, o0i=u0i+u2i;
    float o1r=u1r+u3r, o1i=u1i+u3i;
    float o2r=u0r-u2r, o2i=u0i-u2i;
    float o3r=u1r-u3r, o3i=u1i-u3i;
    float w1i = INV ?  S2 : -S2;
    { float a=o1r, bb=o1i; o1r = S2*a - w1i*bb; o1i = S2*bb + w1i*a; }
    { float a=o2r, bb=o2i; if (INV) { o2r = -bb; o2i = a; } else { o2r = bb; o2i = -a; } }
    { float a=o3r, bb=o3i; o3r = -S2*a - w1i*bb; o3i = -S2*bb + w1i*a; }
    float yr[8], yi[8];
    yr[0]=e0r+o0r; yi[0]=e0i+o0i;
    yr[1]=e1r+o1r; yi[1]=e1i+o1i;
    yr[2]=e2r+o2r; yi[2]=e2i+o2i;
    yr[3]=e3r+o3r; yi[3]=e3i+o3i;
    yr[4]=e0r-o0r; yi[4]=e0i-o0i;
    yr[5]=e1r-o1r; yi[5]=e1i-o1i;
    yr[6]=e2r-o2r; yi[6]=e2i-o2i;
    yr[7]=e3r-o3r; yi[7]=e3i-o3i;
    if (!INV) {
#pragma unroll
        for (int r = 1; r < 8; r++) {
            float wr = twr[M*j*r], wi = twi[M*j*r];
            float a = yr[r], bb = yi[r];
            yr[r] = a*wr - bb*wi;
            yi[r] = a*wi + bb*wr;
        }
    }
#pragma unroll
    for (int r = 0; r < 8; r++) { Ar[idx[r]] = yr[r]; Ai[idx[r]] = yi[r]; }
}

__device__ __forceinline__ void fft8_fwd_dim(float* Ar, float* Ai,
                                             const float* twr, const float* twi,
                                             int tid, bool col) {
    fft8s<8,1,false>(Ar, Ai, twr, twi, tid, col); __syncthreads();
    fft8s<1,8,false>(Ar, Ai, twr, twi, tid, col); __syncthreads();
}
__device__ __forceinline__ void fft8_inv_dim(float* Ar, float* Ai,
                                             const float* twr, const float* twi,
                                             int tid, bool col) {
    fft8s<1,8,true>(Ar, Ai, twr, twi, tid, col); __syncthreads();
    fft8s<8,1,true>(Ar, Ai, twr, twi, tid, col); __syncthreads();
}

__device__ __forceinline__ void fft_load_tw64(float* twr, float* twi, int tid) {
    if (tid < 64) {
        float s, c;
        sincosf(-6.28318530717958647692f * (float)tid * (1.0f/64.0f), &s, &c);
        twr[tid] = c; twi[tid] = s;
    }
}

// ---------------- K2: dw 3x3 + BN + ReLU + stats, 2 px/thread ----------
__global__ void __launch_bounds__(256) k_dw(const float* __restrict__ dww,
                                            const float* __restrict__ dwb,
                                            const float* __restrict__ gamma,
                                            const float* __restrict__ beta,
                                            const float* __restrict__ mean,
                                            const float* __restrict__ var) {
    int plane = blockIdx.x;
    int c = plane & (MIDC-1);
    __shared__ float tile[66*66];
    __shared__ float rs[8], rq[8];
    const __half* src = g_buf1h + (size_t)plane*HW;
    int tid = threadIdx.x;
#pragma unroll
    for (int i = 0; i < 8; i++) {
        int e = tid + i*256;
        int p = e*2;
        int r = p >> 6, cc = p & 63;
        __half2 h = *(const __half2*)(src + p);
        float2 f = __half22float2(h);
        float* t = &tile[(r+1)*66 + cc + 1];
        t[0] = f.x; t[1] = f.y;
    }
    for (int i = tid; i < 260; i += 256) {
        int a;
        if (i < 66)       a = i;
        else if (i < 132) a = 65*66 + (i - 66);
        else if (i < 196) a = (i - 131)*66;
        else              a = (i - 195)*66 + 65;
        tile[a] = 0.f;
    }
    __syncthreads();
    float w0 = dww[c*9+0], w1 = dww[c*9+1], w2 = dww[c*9+2];
    float w3 = dww[c*9+3], w4 = dww[c*9+4], w5 = dww[c*9+5];
    float w6 = dww[c*9+6], w7 = dww[c*9+7], w8 = dww[c*9+8];
    float scale = gamma[c] * rsqrtf(var[c] + 1e-5f);
    float shift = beta[c] - mean[c]*scale;
    float bia = dwb[c];
    float s = 0.f, sq = 0.f;
    __half* dst = g_xr_h + (size_t)plane*HW;
#pragma unroll
    for (int i = 0; i < 8; i++) {
        int e = tid + i*256;
        int p = e*2;
        int py = p >> 6, px = p & 63;
        const float* t0 = &tile[py*66 + px];
        float r00=t0[0],  r01=t0[1],  r02=t0[2],  r03=t0[3];
        float r10=t0[66], r11=t0[67], r12=t0[68], r13=t0[69];
        float r20=t0[132],r21=t0[133],r22=t0[134],r23=t0[135];
        float a0 = r00*w0 + r01*w1 + r02*w2
                 + r10*w3 + r11*w4 + r12*w5
                 + r20*w6 + r21*w7 + r22*w8;
        float a1 = r01*w0 + r02*w1 + r03*w2
                 + r11*w3 + r12*w4 + r13*w5
                 + r21*w6 + r22*w7 + r23*w8;
        a0 = fmaxf((a0 + bia)*scale + shift, 0.f);
        a1 = fmaxf((a1 + bia)*scale + shift, 0.f);
        *(__half2*)(dst + p) = __floats2half2_rn(a0, a1);
        s += a0 + a1; sq += a0*a0 + a1*a1;
    }
#pragma unroll
    for (int o = 16; o; o >>= 1) {
        s  += __shfl_xor_sync(0xffffffffu, s,  o);
        sq += __shfl_xor_sync(0xffffffffu, sq, o);
    }
    int wid = tid >> 5;
    if ((tid & 31) == 0) { rs[wid] = s; rq[wid] = sq; }
    __syncthreads();
    if (tid == 0) {
        float ts = 0.f, tq = 0.f;
#pragma unroll
        for (int w = 0; w < 8; w++) { ts += rs[w]; tq += rq[w]; }
        g_means[plane] = ts * (1.f/4096.f);
        g_nrm[plane]   = sqrtf(tq);   // Parseval
    }
}

// ---- K7: packed-real fwm + inline SE gate, 2 planes/CTA, radix-8, 512 threads ----
__global__ void __launch_bounds__(512) k_fwm2(const float* __restrict__ gw1,
                                              const float* __restrict__ gb1,
                                              const float* __restrict__ gw2,
                                              const float* __restrict__ gb2) {
    __shared__ float Ar[64*65], Ai[64*65], twr[64], twi[64];
    __shared__ int mate[64];
    __shared__ float smn[MIDC], sh[32], sgate[2];
    int pp = blockIdx.x;
    int plane0 = pp * 2;
    int b = plane0 >> 8, c0 = plane0 & (MIDC-1);
    int tid = threadIdx.x;
    const __half* x0 = g_xr_h + (size_t)plane0*HW;
    const __half* x1 = x0 + HW;
#pragma unroll
    for (int i = 0; i < 8; i++) {
        int p = tid + i*512; int r = p >> 6, cc = p & 63;
        Ar[r*65+cc] = __half2float(x0[p]);
        Ai[r*65+cc] = __half2float(x1[p]);
    }
    fft_load_tw64(twr, twi, tid);
    if (tid < 64) {
        int rv = ((tid & 7) << 3) | (tid >> 3);
        int nk = (64 - rv) & 63;
        mate[tid] = ((nk & 7) << 3) | (nk >> 3);
    }
    if (tid >= 64 && tid < 64 + MIDC) smn[tid - 64] = g_means[b*MIDC + tid - 64];
    __syncthreads();
    // inline SE gate: layer 1 on threads < 256 (8 threads per output)
    if (tid < 256) {
        int o = tid >> 3, part = tid & 7;
        const float* wr = gw1 + o*MIDC + part*32;
        const float* mr = smn + part*32;
        float a = 0.f;
#pragma unroll
        for (int j = 0; j < 32; j++) a += wr[j]*mr[j];
#pragma unroll
        for (int off = 4; off; off >>= 1)
            a += __shfl_down_sync(0xffffffffu, a, off, 8);
        if (part == 0) sh[o] = fmaxf(a + gb1[o], 0.f);
    }
    __syncthreads();
    if (tid < 2) {
        int ch = c0 + tid;
        float a = gb2[ch];
        const float* wr = gw2 + ch*32;
#pragma unroll
        for (int j = 0; j < 32; j++) a += wr[j]*sh[j];
        sgate[tid] = 1.f / (1.f + expf(-a));
    }
    // FFT stages below all end in __syncthreads, so sgate is visible at the end
    fft8_fwd_dim(Ar, Ai, twr, twi, tid, false);
    fft8_fwd_dim(Ar, Ai, twr, twi, tid, true);
#pragma unroll
    for (int i = 0; i < 8; i++) {
        int p = tid + i*512; int r = p >> 6, cc = p & 63;
        int mr = mate[r], mc = mate[cc];
        int fm = mr*64 + mc;
        if (p <= fm) {
            int a  = r*65 + cc;
            int am = mr*65 + mc;
            float zpr = Ar[a],  zpi = Ai[a];
            float zmr = Ar[am], zmi = Ai[am];
            float f1r = 0.5f*(zpr + zmr), f1i = 0.5f*(zpi - zmi);
            float f2r = 0.5f*(zpi + zmi), f2i = 0.5f*(zmr - zpr);
            float W1r = f1r*f1r - f1i*f1i, W1i = 2.f*f1r*f1i;
            float W2r = f2r*f2r - f2i*f2i, W2i = 2.f*f2r*f2i;
            Ar[a]  = W1r - W2i;  Ai[a]  = W1i + W2r;
            Ar[am] = W1r + W2i;  Ai[am] = W2r - W1i;
        }
    }
    __syncthreads();
    fft8_inv_dim(Ar, Ai, twr, twi, tid, false);
    fft8_inv_dim(Ar, Ai, twr, twi, tid, true);
    float sc0 = sgate[0] * (1.f/262144.f);
    float sc1 = sgate[1] * (1.f/262144.f);
    __nv_bfloat16* dst0 = g_fused_bf + ((size_t)b*INDIM + MIDC + c0)*HW;
    __nv_bfloat16* dst1 = dst0 + HW;
#pragma unroll
    for (int i = 0; i < 8; i++) {
        int p = tid + i*512; int r = p >> 6, cc = p & 63;
        int a = r*65 + cc;
        dst0[p] = __float2bfloat16(Ar[a] * sc0);
        dst1[p] = __float2bfloat16(Ai[a] * sc1);
    }
}

// ------- K4a: spatial Gram via wmma: C[32,32] = X[32,512] * Y^T ---
#define GX_STRIDE 72
__global__ void __launch_bounds__(256) k_gram() {
    int sl = blockIdx.x, h = blockIdx.y, b = blockIdx.z;
    size_t base = ((size_t)b*MIDC + h*32) * HW;
    __shared__ __align__(16) __half sX[32*GX_STRIDE];
    __shared__ __align__(16) __half sY[32*GX_STRIDE];
    __shared__ float sC[8][256];
    int tid = threadIdx.x;
    int warp = tid >> 5;
    int tile = warp & 3;
    int kgrp = warp >> 2;
    int ti = tile >> 1, tj = tile & 1;

    wmma::fragment<wmma::accumulator, 16, 16, 16, float> acc;
    wmma::fill_fragment(acc, 0.0f);

    for (int it = 0; it < 8; it++) {
        int o = sl*512 + it*64;
        int row = o >> 6;
        int grow = (64 - row) & 63;
        __syncthreads();
        for (int idx = tid; idx < 1024; idx += 256) {
            int cc = idx >> 5, nn = (idx & 31) * 2;
            __half2 hx = *(const __half2*)(&g_xr_h[base + (size_t)cc*HW + o + nn]);
            sX[cc*GX_STRIDE + nn]     = __low2half(hx);
            sX[cc*GX_STRIDE + nn + 1] = __high2half(hx);
            __half2 hy = *(const __half2*)(&g_xr_h[base + (size_t)cc*HW + grow*64 + nn]);
            sY[cc*GX_STRIDE + ((64 - nn) & 63)] = __low2half(hy);
            sY[cc*GX_STRIDE + 63 - nn]          = __high2half(hy);
        }
        __syncthreads();
        if ((it & 1) == kgrp) {
#pragma unroll
            for (int ks = 0; ks < 4; ks++) {
                wmma::fragment<wmma::matrix_a, 16, 16, 16, __half, wmma::row_major> af;
                wmma::fragment<wmma::matrix_b, 16, 16, 16, __half, wmma::col_major> bf;
                wmma::load_matrix_sync(af, sX + (ti*16)*GX_STRIDE + ks*16, GX_STRIDE);
                wmma::load_matrix_sync(bf, sY + (tj*16)*GX_STRIDE + ks*16, GX_STRIDE);
                wmma::mma_sync(acc, af, bf, acc);
            }
        }
    }
    __syncthreads();
    wmma::store_matrix_sync(sC[warp], acc, 16, wmma::mem_row_major);
    __syncthreads();
    float* part = g_gram_part + ((size_t)(b*HEADS + h)*8 + sl)*1024;
    for (int e = tid; e < 1024; e += 256) {
        int c = e >> 5, d = e & 31;
        int t = (c >> 4)*2 + (d >> 4);
        int lr = c & 15, lc = d & 15;
        part[e] = sC[t][lr*16 + lc] + sC[t+4][lr*16 + lc];
    }
}

// ---------------- K4b: reduce partials + normalize + softmax ----------------
__global__ void __launch_bounds__(256) k_soft(const float* __restrict__ temp) {
    int h = blockIdx.x, b = blockIdx.y;
    __shared__ float sA[32][33], sN[32];
    int tid = threadIdx.x;
    if (tid < 32) sN[tid] = fmaxf(g_nrm[b*MIDC + h*32 + tid], 1e-12f);
    __syncthreads();
    float tK = temp[h];
    const float* part = g_gram_part + (size_t)(b*HEADS + h)*8*1024;
#pragma unroll
    for (int q = 0; q < 4; q++) {
        int e = tid*4 + q;
        int c = e >> 5, d = e & 31;
        float v = 0.f;
#pragma unroll
        for (int s = 0; s < 8; s++) v += part[s*1024 + e];
        sA[c][d] = v * tK / (sN[c] * sN[d]);
    }
    __syncthreads();
    int lane = tid & 31;
    float* aw = g_attnW + (size_t)(b*HEADS + h)*1024;
#pragma unroll
    for (int rr = 0; rr < 4; rr++) {
        int row = (tid >> 5)*4 + rr;
        float v = sA[row][lane];
        float mx = v;
#pragma unroll
        for (int o = 16; o; o >>= 1) mx = fmaxf(mx, __shfl_xor_sync(0xffffffffu, mx, o));
        float e = expf(v - mx);
        float smv = e;
#pragma unroll
        for (int o = 16; o; o >>= 1) smv += __shfl_xor_sync(0xffffffffu, smv, o);
        aw[row*32 + lane] = e / smv;
    }
}

// ---- K4c: spatial mix via wmma: out[32,64] = A[32,32] * S[32,64] per chunk ----
#define MS_STRIDE 72
#define MA_STRIDE 40
#define MC_STRIDE 68
__global__ void __launch_bounds__(256) k_mix() {
    int sl = blockIdx.x, h = blockIdx.y, b = blockIdx.z;
    size_t base = ((size_t)b*MIDC + h*32) * HW;
    __shared__ __align__(16) __half sA[32*MA_STRIDE];
    __shared__ __align__(16) __half sS[32*MS_STRIDE];
    __shared__ float sC[32*MC_STRIDE];
    int tid = threadIdx.x;
    const float* aw = g_attnW + (size_t)(b*HEADS + h)*1024;
#pragma unroll
    for (int q = 0; q < 4; q++) {
        int e = tid*4 + q;
        sA[(e >> 5)*MA_STRIDE + (e & 31)] = __float2half(aw[e]);
    }
    int warp = tid >> 5;
    int ti = warp >> 2, tj = warp & 3;
    size_t fb2 = ((size_t)b*INDIM + h*32) * HW;
    for (int it = 0; it < 8; it++) {
        int o = sl*512 + it*64;
        int row = o >> 6;
        int grow = (64 - row) & 63;
        __syncthreads();
        for (int idx = tid; idx < 1024; idx += 256) {
            int cc = idx >> 5, nn = (idx & 31) * 2;
            float2 ff = __half22float2(*(const __half2*)(&g_xr_h[base + (size_t)cc*HW + o + nn]));
            const __half* rv = &g_xr_h[base + (size_t)cc*HW + grow*64];
            float r0 = __half2float(rv[(64 - nn) & 63]);
            float r1 = __half2float(rv[63 - nn]);
            *(__half2*)(&sS[cc*MS_STRIDE + nn]) =
                __floats2half2_rn(0.5f*(ff.x + r0), 0.5f*(ff.y + r1));
        }
        __syncthreads();
        {
            wmma::fragment<wmma::accumulator, 16, 16, 16, float> acc;
            wmma::fill_fragment(acc, 0.0f);
#pragma unroll
            for (int ks = 0; ks < 2; ks++) {
                wmma::fragment<wmma::matrix_a, 16, 16, 16, __half, wmma::row_major> af;
                wmma::fragment<wmma::matrix_b, 16, 16, 16, __half, wmma::row_major> bf;
                wmma::load_matrix_sync(af, sA + (ti*16)*MA_STRIDE + ks*16, MA_STRIDE);
                wmma::load_matrix_sync(bf, sS + (ks*16)*MS_STRIDE + tj*16, MS_STRIDE);
                wmma::mma_sync(acc, af, bf, acc);
            }
            wmma::store_matrix_sync(sC + (ti*16)*MC_STRIDE + tj*16, acc,
                                    MC_STRIDE, wmma::mem_row_major);
        }
        __syncthreads();
        for (int idx = tid; idx < 1024; idx += 256) {
            int cc = idx >> 5, nn = (idx & 31) * 2;
            __nv_bfloat162 q = __floats2bfloat162_rn(sC[cc*MC_STRIDE + nn],
                                                     sC[cc*MC_STRIDE + nn + 1]);
            *(uint32_t*)(&g_fused_bf[fb2 + (size_t)cc*HW + o + nn]) = *(uint32_t*)&q;
        }
    }
}

// ---------------- launch ----------------
extern "C" void kernel_launch(void* const* d_in, const int* in_sizes, int n_in,
                              void* d_out, int out_size) {
    (void)in_sizes; (void)n_in; (void)out_size;
    const float* x        = (const float*)d_in[0];
    const float* reduce_w = (const float*)d_in[1];
    const float* reduce_b = (const float*)d_in[2];
    const float* dw_w     = (const float*)d_in[3];
    const float* dw_b     = (const float*)d_in[4];
    const float* bn_gamma = (const float*)d_in[5];
    const float* bn_beta  = (const float*)d_in[6];
    const float* bn_mean  = (const float*)d_in[7];
    const float* bn_var   = (const float*)d_in[8];
    const float* gate_w1  = (const float*)d_in[9];
    const float* gate_b1  = (const float*)d_in[10];
    const float* gate_w2  = (const float*)d_in[11];
    const float* gate_b2  = (const float*)d_in[12];
    const float* temp     = (const float*)d_in[13];
    const float* post_w   = (const float*)d_in[14];
    const float* post_b   = (const float*)d_in[15];
    float* out = (float*)d_out;

    cudaFuncSetAttribute((const void*)k_gemm_red,
                         cudaFuncAttributeMaxDynamicSharedMemorySize, GEMM_SMEM);
    cudaFuncSetAttribute((const void*)k_gemm_pipe,
                         cudaFuncAttributeMaxDynamicSharedMemorySize, GEMM_SMEM);

    __nv_bfloat16 *p_fbf, *p_wred, *p_wpost;
    cudaGetSymbolAddress((void**)&p_fbf,   g_fused_bf);
    cudaGetSymbolAddress((void**)&p_wred,  g_wred);
    cudaGetSymbolAddress((void**)&p_wpost, g_wpost);
    __half* p_buf1h;
    cudaGetSymbolAddress((void**)&p_buf1h, g_buf1h);

    cudaStream_t s2;
    cudaStreamCreateWithFlags(&s2, cudaStreamNonBlocking);
    cudaEvent_t e0, e1, e2;
    cudaEventCreateWithFlags(&e0, cudaEventDisableTiming);
    cudaEventCreateWithFlags(&e1, cudaEventDisableTiming);
    cudaEventCreateWithFlags(&e2, cudaEventDisableTiming);

    // fork side stream at entry
    cudaEventRecord(e0, 0);
    cudaStreamWaitEvent(s2, e0, 0);

    // side: post-weight conversion (only needed by gemm_pipe)
    k_cvt<<<(INDIM*2*MIDC/4 + 255)/256, 256, 0, s2>>>(post_w, p_wpost, INDIM*2*MIDC);

    // main: reduce-weight conversion -> reduce GEMM (M=128) -> dw
    k_cvt<<<(MIDC*INDIM/4 + 255)/256, 256>>>(reduce_w, p_wred, MIDC*INDIM);
    k_gemm_red<<<dim3(32, 2, BATCH), 256, GEMM_SMEM>>>(
        p_wred, x, reduce_b, p_buf1h, MIDC);
    k_dw<<<BATCH*MIDC, 256>>>(dw_w, dw_b, bn_gamma, bn_beta, bn_mean, bn_var);

    // fork after dw: branch A (fwm2, gate inlined) on side stream
    cudaEventRecord(e1, 0);
    cudaStreamWaitEvent(s2, e1, 0);
    k_fwm2<<<BATCH*MIDC/2, 512, 0, s2>>>(gate_w1, gate_b1, gate_w2, gate_b2);

    // branch B (gram -> soft -> mix) on main
    k_gram<<<dim3(8, HEADS, BATCH), 256>>>();
    k_soft<<<dim3(HEADS, BATCH), 256>>>(temp);
    k_mix<<<dim3(8, HEADS, BATCH), 256>>>();

    // join: post GEMM needs both halves of fused + wpost
    cudaEventRecord(e2, s2);
    cudaStreamWaitEvent(0, e2, 0);
    k_gemm_pipe<<<dim3(32, 4, BATCH), 256, GEMM_SMEM>>>(
        p_wpost, p_fbf, post_b, x, out, INDIM);
}

// round 16
// speedup vs baseline: 1.1486x; 1.1301x over previous
#include <cuda_runtime.h>
#include <cuda_bf16.h>
#include <cuda_fp16.h>
#include <mma.h>
#include <math.h>
#include <stdint.h>

using namespace nvcuda;

#define BATCH 16
#define INDIM 512
#define MIDC  256
#define HW    4096
#define HEADS 8

// ---------------- scratch (device globals; no allocation) ----------------
__device__ __half g_buf1h[BATCH*MIDC*HW];   // reduce-GEMM output (pre-dw), fp16
__device__ __half g_xr_h[BATCH*MIDC*HW];    // xr (post dw+BN+ReLU), fp16, spatial
__device__ float  g_means[BATCH*MIDC];
__device__ float  g_nrm  [BATCH*MIDC];
__device__ float  g_gate [BATCH*MIDC];
__device__ float  g_gram_part[BATCH*HEADS*8*1024];
__device__ __nv_bfloat16 g_fused_bf[BATCH*INDIM*HW]; // [attn_out | gated fwm]
__device__ __nv_bfloat16 g_wred    [MIDC*INDIM];
__device__ __nv_bfloat16 g_wpost   [INDIM*2*MIDC];

// ================= GEMM common =================
#define AS_STRIDE 40
#define BS_STRIDE 136
#define BF_STRIDE 132
#define CS_STRIDE 132
#define GEMM_SMEM (128*CS_STRIDE*4)

__device__ __forceinline__ void cp16(void* sdst, const void* gsrc) {
    uint32_t a = (uint32_t)__cvta_generic_to_shared(sdst);
    asm volatile("cp.async.cg.shared.global [%0], [%1], 16;\n" :: "r"(a), "l"(gsrc));
}
#define CP_COMMIT() asm volatile("cp.async.commit_group;\n" ::: "memory")
#define CP_WAIT(n)  asm volatile("cp.async.wait_group %0;\n" :: "n"(n) : "memory")

__device__ __forceinline__ void mma_step(
    const __nv_bfloat16* As, const __nv_bfloat16* Bs, int wm, int wn,
    wmma::fragment<wmma::accumulator, 16, 16, 16, float> acc[2][4]) {
#pragma unroll
    for (int ks = 0; ks < 2; ks++) {
        wmma::fragment<wmma::matrix_a, 16, 16, 16, __nv_bfloat16, wmma::row_major> af[2];
        wmma::fragment<wmma::matrix_b, 16, 16, 16, __nv_bfloat16, wmma::row_major> bf[4];
#pragma unroll
        for (int i = 0; i < 2; i++)
            wmma::load_matrix_sync(af[i], As + (wm*32 + i*16) * AS_STRIDE + ks*16, AS_STRIDE);
#pragma unroll
        for (int j = 0; j < 4; j++)
            wmma::load_matrix_sync(bf[j], Bs + (ks*16) * BS_STRIDE + wn*64 + j*16, BS_STRIDE);
#pragma unroll
        for (int i = 0; i < 2; i++)
#pragma unroll
            for (int j = 0; j < 4; j++)
                wmma::mma_sync(acc[i][j], af[i], bf[j], acc[i][j]);
    }
}

// ---------------- reduce GEMM: fp32 act, cp.async-staged + smem convert (M=128) ----
__global__ void __launch_bounds__(256)
k_gemm_red(const __nv_bfloat16* __restrict__ W,
           const float* __restrict__ act,
           const float* __restrict__ bias,
           __half* __restrict__ out,
           int Mtot) {
    extern __shared__ char sm[];
    __nv_bfloat16* As0 = (__nv_bfloat16*)sm;
    float*         Bf0 = (float*)(sm + 2*128*AS_STRIDE*2);
    __nv_bfloat16* Bs  = (__nv_bfloat16*)(sm + 2*128*AS_STRIDE*2 + 2*32*BF_STRIDE*4);
    float*         Cs  = (float*)sm;

    int tid = threadIdx.x;
    int w   = tid >> 5;
    int wm  = w & 3;
    int wn  = w >> 2;
    int nb = blockIdx.x * 128, mb = blockIdx.y * 128, b = blockIdx.z;

    const __nv_bfloat16* Ag = W + (size_t)mb * 512;
    const float* Bg = act + (size_t)b * 512 * 4096 + nb;

    int ar0 = tid >> 2,  ac0 = (tid & 3) * 8;
    int br0 = tid >> 5,  bs0 = (tid & 31) * 4;

    wmma::fragment<wmma::accumulator, 16, 16, 16, float> acc[2][4];
#pragma unroll
    for (int i = 0; i < 2; i++)
#pragma unroll
        for (int j = 0; j < 4; j++) wmma::fill_fragment(acc[i][j], 0.0f);

    {
#pragma unroll
        for (int t = 0; t < 2; t++) {
            int r = ar0 + t*64;
            cp16(As0 + r*AS_STRIDE + ac0, Ag + (size_t)r*512 + ac0);
        }
#pragma unroll
        for (int t = 0; t < 4; t++) {
            int r = br0 + t*8;
            cp16(Bf0 + r*BF_STRIDE + bs0, Bg + (size_t)r*4096 + bs0);
        }
        CP_COMMIT();
    }

    for (int it = 0; it < 16; it++) {
        int cur = it & 1;
        if (it < 15) {
            int kc = (it + 1) * 32;
            __nv_bfloat16* As = As0 + (cur^1)*128*AS_STRIDE;
            float*         Bf = Bf0 + (cur^1)*32*BF_STRIDE;
#pragma unroll
            for (int t = 0; t < 2; t++) {
                int r = ar0 + t*64;
                cp16(As + r*AS_STRIDE + ac0, Ag + (size_t)r*512 + kc + ac0);
            }
#pragma unroll
            for (int t = 0; t < 4; t++) {
                int r = br0 + t*8;
                cp16(Bf + r*BF_STRIDE + bs0, Bg + (size_t)(kc + r)*4096 + bs0);
            }
            CP_COMMIT();
            CP_WAIT(1);
        } else {
            CP_WAIT(0);
        }
        __syncthreads();
        const float* Bf = Bf0 + cur*32*BF_STRIDE;
#pragma unroll
        for (int t = 0; t < 8; t++) {
            int e2 = (tid + t*256) * 2;
            int r = e2 >> 7, c = e2 & 127;
            __nv_bfloat162 pk = __floats2bfloat162_rn(Bf[r*BF_STRIDE + c],
                                                      Bf[r*BF_STRIDE + c + 1]);
            *(uint32_t*)(Bs + r*BS_STRIDE + c) = *(uint32_t*)&pk;
        }
        __syncthreads();
        mma_step(As0 + cur*128*AS_STRIDE, Bs, wm, wn, acc);
        __syncthreads();
    }
#pragma unroll
    for (int i = 0; i < 2; i++)
#pragma unroll
        for (int j = 0; j < 4; j++)
            wmma::store_matrix_sync(Cs + (wm*32 + i*16) * CS_STRIDE + wn*64 + j*16,
                                    acc[i][j], CS_STRIDE, wmma::mem_row_major);
    __syncthreads();
#pragma unroll
    for (int t = 0; t < 16; t++) {
        int id = tid + t * 256;
        int r = id >> 5, c = (id & 31) * 4;
        float bi = bias[mb + r];
        float4 v = *(float4*)(Cs + r * CS_STRIDE + c);
        __half2 h0 = __floats2half2_rn(v.x + bi, v.y + bi);
        __half2 h1 = __floats2half2_rn(v.z + bi, v.w + bi);
        uint2 pk; pk.x = *(uint32_t*)&h0; pk.y = *(uint32_t*)&h1;
        size_t off = ((size_t)b * Mtot + mb + r) * 4096 + nb + c;
        *(uint2*)(out + off) = pk;
    }
}

// ---------------- post GEMM: bf16 act, cp.async 2-stage pipeline ----------------
__global__ void __launch_bounds__(256)
k_gemm_pipe(const __nv_bfloat16* __restrict__ W,
            const __nv_bfloat16* __restrict__ act,
            const float* __restrict__ bias,
            const float* __restrict__ resid,
            float* __restrict__ out,
            int Mtot) {
    extern __shared__ char sm[];
    __nv_bfloat16* As0 = (__nv_bfloat16*)sm;
    __nv_bfloat16* Bs0 = (__nv_bfloat16*)(sm + 2*128*AS_STRIDE*2);
    float*         Cs  = (float*)sm;

    int tid = threadIdx.x;
    int w   = tid >> 5;
    int wm  = w & 3;
    int wn  = w >> 2;
    int nb = blockIdx.x * 128, mb = blockIdx.y * 128, b = blockIdx.z;

    const __nv_bfloat16* Ag = W + (size_t)mb * 512;
    const __nv_bfloat16* Bg = act + (size_t)b * 512 * 4096 + nb;

    int ar0 = tid >> 2,  ac0 = (tid & 3) * 8;
    int br0 = tid >> 4,  bc0 = (tid & 15) * 8;

    wmma::fragment<wmma::accumulator, 16, 16, 16, float> acc[2][4];
#pragma unroll
    for (int i = 0; i < 2; i++)
#pragma unroll
        for (int j = 0; j < 4; j++) wmma::fill_fragment(acc[i][j], 0.0f);

    {
#pragma unroll
        for (int t = 0; t < 2; t++) {
            int r = ar0 + t*64;
            cp16(As0 + r*AS_STRIDE + ac0, Ag + (size_t)r*512 + ac0);
        }
#pragma unroll
        for (int t = 0; t < 2; t++) {
            int r = br0 + t*16;
            cp16(Bs0 + r*BS_STRIDE + bc0, Bg + (size_t)r*4096 + bc0);
        }
        CP_COMMIT();
    }

    for (int it = 0; it < 16; it++) {
        int cur = it & 1;
        if (it < 15) {
            int kc = (it + 1) * 32;
            __nv_bfloat16* As = As0 + (cur^1)*128*AS_STRIDE;
            __nv_bfloat16* Bs = Bs0 + (cur^1)*32*BS_STRIDE;
#pragma unroll
            for (int t = 0; t < 2; t++) {
                int r = ar0 + t*64;
                cp16(As + r*AS_STRIDE + ac0, Ag + (size_t)r*512 + kc + ac0);
            }
#pragma unroll
            for (int t = 0; t < 2; t++) {
                int r = br0 + t*16;
                cp16(Bs + r*BS_STRIDE + bc0, Bg + (size_t)(kc + r)*4096 + bc0);
            }
            CP_COMMIT();
            CP_WAIT(1);
        } else {
            CP_WAIT(0);
        }
        __syncthreads();
        mma_step(As0 + cur*128*AS_STRIDE, Bs0 + cur*32*BS_STRIDE, wm, wn, acc);
        __syncthreads();
    }
#pragma unroll
    for (int i = 0; i < 2; i++)
#pragma unroll
        for (int j = 0; j < 4; j++)
            wmma::store_matrix_sync(Cs + (wm*32 + i*16) * CS_STRIDE + wn*64 + j*16,
                                    acc[i][j], CS_STRIDE, wmma::mem_row_major);
    __syncthreads();
#pragma unroll
    for (int t = 0; t < 16; t++) {
        int id = tid + t * 256;
        int r = id >> 5, c = (id & 31) * 4;
        float bi = bias[mb + r];
        float4 v = *(float4*)(Cs + r * CS_STRIDE + c);
        v.x += bi; v.y += bi; v.z += bi; v.w += bi;
        size_t off = ((size_t)b * Mtot + mb + r) * 4096 + nb + c;
        float4 rr = *(const float4*)(resid + off);
        v.x += rr.x; v.y += rr.y; v.z += rr.z; v.w += rr.w;
        *(float4*)(out + off) = v;
    }
}

// ---------------- weight conversion ----------------
__global__ void __launch_bounds__(256) k_cvt(const float* __restrict__ src,
                                             __nv_bfloat16* __restrict__ dst, int n) {
    int i = (blockIdx.x * 256 + threadIdx.x) * 4;
    if (i < n) {
        float4 v = *(const float4*)(src + i);
        __nv_bfloat162 p0 = __floats2bfloat162_rn(v.x, v.y);
        __nv_bfloat162 p1 = __floats2bfloat162_rn(v.z, v.w);
        uint2 pk;
        pk.x = *(uint32_t*)&p0; pk.y = *(uint32_t*)&p1;
        *(uint2*)(dst + i) = pk;
    }
}

// ================= radix-8 FFT (64-pt, 2 stages/dim, 512 threads, 1 bfly/thr) ======
template<int Q, int M, bool INV>
__device__ __forceinline__ void fft8s(float* Ar, float* Ai,
                                      const float* twr, const float* twi,
                                      int tid, bool col) {
    const float S2 = 0.70710678118654752440f;
    int bf = tid;
    int line = bf & 63;
    int j8 = bf >> 6;
    int blk = j8 / Q, j = j8 - blk * Q;
    int base = blk * (8 * Q) + j;
    int idx[8];
#pragma unroll
    for (int r = 0; r < 8; r++) {
        int p = base + r * Q;
        idx[r] = col ? p*65 + line : line*65 + p;
    }
    float xr[8], xi[8];
#pragma unroll
    for (int r = 0; r < 8; r++) { xr[r] = Ar[idx[r]]; xi[r] = Ai[idx[r]]; }
    if (INV) {
#pragma unroll
        for (int r = 1; r < 8; r++) {
            float wr = twr[M*j*r], wi = twi[M*j*r];
            float a = xr[r], bb = xi[r];
            xr[r] = a*wr + bb*wi;
            xi[r] = bb*wr - a*wi;
        }
    }
    float t0r=xr[0]+xr[4], t0i=xi[0]+xi[4];
    float t1r=xr[0]-xr[4], t1i=xi[0]-xi[4];
    float t2r=xr[2]+xr[6], t2i=xi[2]+xi[6];
    float d2r=xr[2]-xr[6], d2i=xi[2]-xi[6];
    float t3r, t3i;
    if (INV) { t3r = -d2i; t3i =  d2r; } else { t3r =  d2i; t3i = -d2r; }
    float e0r=t0r+t2r, e0i=t0i+t2i;
    float e1r=t1r+t3r, e1i=t1i+t3i;
    float e2r=t0r-t2r, e2i=t0i-t2i;
    float e3r=t1r-t3r, e3i=t1i-t3i;
    float u0r=xr[1]+xr[5], u0i=xi[1]+xi[5];
    float u1r=xr[1]-xr[5], u1i=xi[1]-xi[5];
    float u2r=xr[3]+xr[7], u2i=xi[3]+xi[7];
    float v2r=xr[3]-xr[7], v2i=xi[3]-xi[7];
    float u3r, u3i;
    if (INV) { u3r = -v2i; u3i =  v2r; } else { u3r =  v2i; u3i = -v2r; }
    float o0r=u0r+u2r, o0i=u0i+u2i;
    float o1r=u1r+u3r, o1i=u1i+u3i;
    float o2r=u0r-u2r, o2i=u0i-u2i;
    float o3r=u1r-u3r, o3i=u1i-u3i;
    float w1i = INV ?  S2 : -S2;
    { float a=o1r, bb=o1i; o1r = S2*a - w1i*bb; o1i = S2*bb + w1i*a; }
    { float a=o2r, bb=o2i; if (INV) { o2r = -bb; o2i = a; } else { o2r = bb; o2i = -a; } }
    { float a=o3r, bb=o3i; o3r = -S2*a - w1i*bb; o3i = -S2*bb + w1i*a; }
    float yr[8], yi[8];
    yr[0]=e0r+o0r; yi[0]=e0i+o0i;
    yr[1]=e1r+o1r; yi[1]=e1i+o1i;
    yr[2]=e2r+o2r; yi[2]=e2i+o2i;
    yr[3]=e3r+o3r; yi[3]=e3i+o3i;
    yr[4]=e0r-o0r; yi[4]=e0i-o0i;
    yr[5]=e1r-o1r; yi[5]=e1i-o1i;
    yr[6]=e2r-o2r; yi[6]=e2i-o2i;
    yr[7]=e3r-o3r; yi[7]=e3i-o3i;
    if (!INV) {
#pragma unroll
        for (int r = 1; r < 8; r++) {
            float wr = twr[M*j*r], wi = twi[M*j*r];
            float a = yr[r], bb = yi[r];
            yr[r] = a*wr - bb*wi;
            yi[r] = a*wi + bb*wr;
        }
    }
#pragma unroll
    for (int r = 0; r < 8; r++) { Ar[idx[r]] = yr[r]; Ai[idx[r]] = yi[r]; }
}

__device__ __forceinline__ void fft8_fwd_dim(float* Ar, float* Ai,
                                             const float* twr, const float* twi,
                                             int tid, bool col) {
    fft8s<8,1,false>(Ar, Ai, twr, twi, tid, col); __syncthreads();
    fft8s<1,8,false>(Ar, Ai, twr, twi, tid, col); __syncthreads();
}
__device__ __forceinline__ void fft8_inv_dim(float* Ar, float* Ai,
                                             const float* twr, const float* twi,
                                             int tid, bool col) {
    fft8s<1,8,true>(Ar, Ai, twr, twi, tid, col); __syncthreads();
    fft8s<8,1,true>(Ar, Ai, twr, twi, tid, col); __syncthreads();
}

__device__ __forceinline__ void fft_load_tw64(float* twr, float* twi, int tid) {
    if (tid < 64) {
        float s, c;
        sincosf(-6.28318530717958647692f * (float)tid * (1.0f/64.0f), &s, &c);
        twr[tid] = c; twi[tid] = s;
    }
}

// ---------------- K2: dw 3x3 + BN + ReLU + stats, 2 px/thread ----------
__global__ void __launch_bounds__(256) k_dw(const float* __restrict__ dww,
                                            const float* __restrict__ dwb,
                                            const float* __restrict__ gamma,
                                            const float* __restrict__ beta,
                                            const float* __restrict__ mean,
                                            const float* __restrict__ var) {
    int plane = blockIdx.x;
    int c = plane & (MIDC-1);
    __shared__ float tile[66*66];
    __shared__ float rs[8], rq[8];
    const __half* src = g_buf1h + (size_t)plane*HW;
    int tid = threadIdx.x;
#pragma unroll
    for (int i = 0; i < 8; i++) {
        int e = tid + i*256;
        int p = e*2;
        int r = p >> 6, cc = p & 63;
        __half2 h = *(const __half2*)(src + p);
        float2 f = __half22float2(h);
        float* t = &tile[(r+1)*66 + cc + 1];
        t[0] = f.x; t[1] = f.y;
    }
    for (int i = tid; i < 260; i += 256) {
        int a;
        if (i < 66)       a = i;
        else if (i < 132) a = 65*66 + (i - 66);
        else if (i < 196) a = (i - 131)*66;
        else              a = (i - 195)*66 + 65;
        tile[a] = 0.f;
    }
    __syncthreads();
    float w0 = dww[c*9+0], w1 = dww[c*9+1], w2 = dww[c*9+2];
    float w3 = dww[c*9+3], w4 = dww[c*9+4], w5 = dww[c*9+5];
    float w6 = dww[c*9+6], w7 = dww[c*9+7], w8 = dww[c*9+8];
    float scale = gamma[c] * rsqrtf(var[c] + 1e-5f);
    float shift = beta[c] - mean[c]*scale;
    float bia = dwb[c];
    float s = 0.f, sq = 0.f;
    __half* dst = g_xr_h + (size_t)plane*HW;
#pragma unroll
    for (int i = 0; i < 8; i++) {
        int e = tid + i*256;
        int p = e*2;
        int py = p >> 6, px = p & 63;
        const float* t0 = &tile[py*66 + px];
        float r00=t0[0],  r01=t0[1],  r02=t0[2],  r03=t0[3];
        float r10=t0[66], r11=t0[67], r12=t0[68], r13=t0[69];
        float r20=t0[132],r21=t0[133],r22=t0[134],r23=t0[135];
        float a0 = r00*w0 + r01*w1 + r02*w2
                 + r10*w3 + r11*w4 + r12*w5
                 + r20*w6 + r21*w7 + r22*w8;
        float a1 = r01*w0 + r02*w1 + r03*w2
                 + r11*w3 + r12*w4 + r13*w5
                 + r21*w6 + r22*w7 + r23*w8;
        a0 = fmaxf((a0 + bia)*scale + shift, 0.f);
        a1 = fmaxf((a1 + bia)*scale + shift, 0.f);
        *(__half2*)(dst + p) = __floats2half2_rn(a0, a1);
        s += a0 + a1; sq += a0*a0 + a1*a1;
    }
#pragma unroll
    for (int o = 16; o; o >>= 1) {
        s  += __shfl_xor_sync(0xffffffffu, s,  o);
        sq += __shfl_xor_sync(0xffffffffu, sq, o);
    }
    int wid = tid >> 5;
    if ((tid & 31) == 0) { rs[wid] = s; rq[wid] = sq; }
    __syncthreads();
    if (tid == 0) {
        float ts = 0.f, tq = 0.f;
#pragma unroll
        for (int w = 0; w < 8; w++) { ts += rs[w]; tq += rq[w]; }
        g_means[plane] = ts * (1.f/4096.f);
        g_nrm[plane]   = sqrtf(tq);   // Parseval
    }
}

// ---- K7: packed-real fwm, 2 planes/CTA, radix-8, 512 threads, gated output ----
// (byte-identical to the R13 version: gate read from g_gate, no inline MLP)
__global__ void __launch_bounds__(512) k_fwm2() {
    __shared__ float Ar[64*65], Ai[64*65], twr[64], twi[64];
    __shared__ int mate[64];
    int pp = blockIdx.x;
    int plane0 = pp * 2;
    int b = plane0 >> 8, c0 = plane0 & (MIDC-1);
    int tid = threadIdx.x;
    const __half* x0 = g_xr_h + (size_t)plane0*HW;
    const __half* x1 = x0 + HW;
#pragma unroll
    for (int i = 0; i < 8; i++) {
        int p = tid + i*512; int r = p >> 6, cc = p & 63;
        Ar[r*65+cc] = __half2float(x0[p]);
        Ai[r*65+cc] = __half2float(x1[p]);
    }
    fft_load_tw64(twr, twi, tid);
    if (tid < 64) {
        int rv = ((tid & 7) << 3) | (tid >> 3);
        int nk = (64 - rv) & 63;
        mate[tid] = ((nk & 7) << 3) | (nk >> 3);
    }
    __syncthreads();
    fft8_fwd_dim(Ar, Ai, twr, twi, tid, false);
    fft8_fwd_dim(Ar, Ai, twr, twi, tid, true);
#pragma unroll
    for (int i = 0; i < 8; i++) {
        int p = tid + i*512; int r = p >> 6, cc = p & 63;
        int mr = mate[r], mc = mate[cc];
        int fm = mr*64 + mc;
        if (p <= fm) {
            int a  = r*65 + cc;
            int am = mr*65 + mc;
            float zpr = Ar[a],  zpi = Ai[a];
            float zmr = Ar[am], zmi = Ai[am];
            float f1r = 0.5f*(zpr + zmr), f1i = 0.5f*(zpi - zmi);
            float f2r = 0.5f*(zpi + zmi), f2i = 0.5f*(zmr - zpr);
            float W1r = f1r*f1r - f1i*f1i, W1i = 2.f*f1r*f1i;
            float W2r = f2r*f2r - f2i*f2i, W2i = 2.f*f2r*f2i;
            Ar[a]  = W1r - W2i;  Ai[a]  = W1i + W2r;
            Ar[am] = W1r + W2i;  Ai[am] = W2r - W1i;
        }
    }
    __syncthreads();
    fft8_inv_dim(Ar, Ai, twr, twi, tid, false);
    fft8_inv_dim(Ar, Ai, twr, twi, tid, true);
    float sc0 = g_gate[b*MIDC + c0]     * (1.f/262144.f);
    float sc1 = g_gate[b*MIDC + c0 + 1] * (1.f/262144.f);
    __nv_bfloat16* dst0 = g_fused_bf + ((size_t)b*INDIM + MIDC + c0)*HW;
    __nv_bfloat16* dst1 = dst0 + HW;
#pragma unroll
    for (int i = 0; i < 8; i++) {
        int p = tid + i*512; int r = p >> 6, cc = p & 63;
        int a = r*65 + cc;
        dst0[p] = __float2bfloat16(Ar[a] * sc0);
        dst1[p] = __float2bfloat16(Ai[a] * sc1);
    }
}

// ---------------- K3: SE gate MLP (parallel reduction) ----------------
__global__ void __launch_bounds__(256) k_gate(const float* __restrict__ w1,
                                              const float* __restrict__ b1,
                                              const float* __restrict__ w2,
                                              const float* __restrict__ b2) {
    int b = blockIdx.x;
    __shared__ float sm[MIDC];
    __shared__ float sh[32];
    int tid = threadIdx.x;
    sm[tid] = g_means[b*MIDC + tid];
    __syncthreads();
    {
        int o = tid >> 3, part = tid & 7;
        const float* wr = w1 + o*MIDC + part*32;
        const float* mr = sm + part*32;
        float a = 0.f;
#pragma unroll
        for (int j = 0; j < 32; j++) a += wr[j]*mr[j];
#pragma unroll
        for (int off = 4; off; off >>= 1)
            a += __shfl_down_sync(0xffffffffu, a, off, 8);
        if (part == 0) sh[o] = fmaxf(a + b1[o], 0.f);
    }
    __syncthreads();
    float a = b2[tid];
    const float* wr = w2 + tid*32;
#pragma unroll
    for (int j = 0; j < 32; j++) a += wr[j]*sh[j];
    g_gate[b*MIDC + tid] = 1.f / (1.f + expf(-a));
}

// ------- K4a: spatial Gram via wmma: C[32,32] = X[32,512] * Y^T ---
#define GX_STRIDE 72
__global__ void __launch_bounds__(256) k_gram() {
    int sl = blockIdx.x, h = blockIdx.y, b = blockIdx.z;
    size_t base = ((size_t)b*MIDC + h*32) * HW;
    __shared__ __align__(16) __half sX[32*GX_STRIDE];
    __shared__ __align__(16) __half sY[32*GX_STRIDE];
    __shared__ float sC[8][256];
    int tid = threadIdx.x;
    int warp = tid >> 5;
    int tile = warp & 3;
    int kgrp = warp >> 2;
    int ti = tile >> 1, tj = tile & 1;

    wmma::fragment<wmma::accumulator, 16, 16, 16, float> acc;
    wmma::fill_fragment(acc, 0.0f);

    for (int it = 0; it < 8; it++) {
        int o = sl*512 + it*64;
        int row = o >> 6;
        int grow = (64 - row) & 63;
        __syncthreads();
        for (int idx = tid; idx < 1024; idx += 256) {
            int cc = idx >> 5, nn = (idx & 31) * 2;
            __half2 hx = *(const __half2*)(&g_xr_h[base + (size_t)cc*HW + o + nn]);
            sX[cc*GX_STRIDE + nn]     = __low2half(hx);
            sX[cc*GX_STRIDE + nn + 1] = __high2half(hx);
            __half2 hy = *(const __half2*)(&g_xr_h[base + (size_t)cc*HW + grow*64 + nn]);
            sY[cc*GX_STRIDE + ((64 - nn) & 63)] = __low2half(hy);
            sY[cc*GX_STRIDE + 63 - nn]          = __high2half(hy);
        }
        __syncthreads();
        if ((it & 1) == kgrp) {
#pragma unroll
            for (int ks = 0; ks < 4; ks++) {
                wmma::fragment<wmma::matrix_a, 16, 16, 16, __half, wmma::row_major> af;
                wmma::fragment<wmma::matrix_b, 16, 16, 16, __half, wmma::col_major> bf;
                wmma::load_matrix_sync(af, sX + (ti*16)*GX_STRIDE + ks*16, GX_STRIDE);
                wmma::load_matrix_sync(bf, sY + (tj*16)*GX_STRIDE + ks*16, GX_STRIDE);
                wmma::mma_sync(acc, af, bf, acc);
            }
        }
    }
    __syncthreads();
    wmma::store_matrix_sync(sC[warp], acc, 16, wmma::mem_row_major);
    __syncthreads();
    float* part = g_gram_part + ((size_t)(b*HEADS + h)*8 + sl)*1024;
    for (int e = tid; e < 1024; e += 256) {
        int c = e >> 5, d = e & 31;
        int t = (c >> 4)*2 + (d >> 4);
        int lr = c & 15, lc = d & 15;
        part[e] = sC[t][lr*16 + lc] + sC[t+4][lr*16 + lc];
    }
}

// ---- K4c: mix with integrated softmax: out[32,64] = softmax(G)[32,32] * S[32,64] ----
#define MS_STRIDE 72
#define MA_STRIDE 40
#define MC_STRIDE 68
__global__ void __launch_bounds__(256) k_mix(const float* __restrict__ temp) {
    int sl = blockIdx.x, h = blockIdx.y, b = blockIdx.z;
    size_t base = ((size_t)b*MIDC + h*32) * HW;
    __shared__ __align__(16) __half sA[32*MA_STRIDE];
    __shared__ __align__(16) __half sS[32*MS_STRIDE];
    __shared__ float sC[32*MC_STRIDE];
    __shared__ float sL[32][33], sN[32];
    int tid = threadIdx.x;
    int lane = tid & 31;
    // integrated softmax (redundant per CTA; partials are L2-resident)
    if (tid < 32) sN[tid] = fmaxf(g_nrm[b*MIDC + h*32 + tid], 1e-12f);
    __syncthreads();
    float tK = temp[h];
    const float* part = g_gram_part + (size_t)(b*HEADS + h)*8*1024;
#pragma unroll
    for (int q = 0; q < 4; q++) {
        int e = tid*4 + q;
        int c = e >> 5, d = e & 31;
        float v = 0.f;
#pragma unroll
        for (int s = 0; s < 8; s++) v += part[s*1024 + e];
        sL[c][d] = v * tK / (sN[c] * sN[d]);
    }
    __syncthreads();
#pragma unroll
    for (int rr = 0; rr < 4; rr++) {
        int row = (tid >> 5)*4 + rr;
        float v = sL[row][lane];
        float mx = v;
#pragma unroll
        for (int o = 16; o; o >>= 1) mx = fmaxf(mx, __shfl_xor_sync(0xffffffffu, mx, o));
        float e = expf(v - mx);
        float smv = e;
#pragma unroll
        for (int o = 16; o; o >>= 1) smv += __shfl_xor_sync(0xffffffffu, smv, o);
        sA[row*MA_STRIDE + lane] = __float2half(e / smv);
    }
    int warp = tid >> 5;
    int ti = warp >> 2, tj = warp & 3;
    size_t fb2 = ((size_t)b*INDIM + h*32) * HW;
    for (int it = 0; it < 8; it++) {
        int o = sl*512 + it*64;
        int row = o >> 6;
        int grow = (64 - row) & 63;
        __syncthreads();   // covers sA writes (iter 0) and prior sC reads
        for (int idx = tid; idx < 1024; idx += 256) {
            int cc = idx >> 5, nn = (idx & 31) * 2;
            float2 ff = __half22float2(*(const __half2*)(&g_xr_h[base + (size_t)cc*HW + o + nn]));
            const __half* rv = &g_xr_h[base + (size_t)cc*HW + grow*64];
            float r0 = __half2float(rv[(64 - nn) & 63]);
            float r1 = __half2float(rv[63 - nn]);
            *(__half2*)(&sS[cc*MS_STRIDE + nn]) =
                __floats2half2_rn(0.5f*(ff.x + r0), 0.5f*(ff.y + r1));
        }
        __syncthreads();
        {
            wmma::fragment<wmma::accumulator, 16, 16, 16, float> acc;
            wmma::fill_fragment(acc, 0.0f);
#pragma unroll
            for (int ks = 0; ks < 2; ks++) {
                wmma::fragment<wmma::matrix_a, 16, 16, 16, __half, wmma::row_major> af;
                wmma::fragment<wmma::matrix_b, 16, 16, 16, __half, wmma::row_major> bf;
                wmma::load_matrix_sync(af, sA + (ti*16)*MA_STRIDE + ks*16, MA_STRIDE);
                wmma::load_matrix_sync(bf, sS + (ks*16)*MS_STRIDE + tj*16, MS_STRIDE);
                wmma::mma_sync(acc, af, bf, acc);
            }
            wmma::store_matrix_sync(sC + (ti*16)*MC_STRIDE + tj*16, acc,
                                    MC_STRIDE, wmma::mem_row_major);
        }
        __syncthreads();
        for (int idx = tid; idx < 1024; idx += 256) {
            int cc = idx >> 5, nn = (idx & 31) * 2;
            __nv_bfloat162 q = __floats2bfloat162_rn(sC[cc*MC_STRIDE + nn],
                                                     sC[cc*MC_STRIDE + nn + 1]);
            *(uint32_t*)(&g_fused_bf[fb2 + (size_t)cc*HW + o + nn]) = *(uint32_t*)&q;
        }
    }
}

// ---------------- launch ----------------
extern "C" void kernel_launch(void* const* d_in, const int* in_sizes, int n_in,
                              void* d_out, int out_size) {
    (void)in_sizes; (void)n_in; (void)out_size;
    const float* x        = (const float*)d_in[0];
    const float* reduce_w = (const float*)d_in[1];
    const float* reduce_b = (const float*)d_in[2];
    const float* dw_w     = (const float*)d_in[3];
    const float* dw_b     = (const float*)d_in[4];
    const float* bn_gamma = (const float*)d_in[5];
    const float* bn_beta  = (const float*)d_in[6];
    const float* bn_mean  = (const float*)d_in[7];
    const float* bn_var   = (const float*)d_in[8];
    const float* gate_w1  = (const float*)d_in[9];
    const float* gate_b1  = (const float*)d_in[10];
    const float* gate_w2  = (const float*)d_in[11];
    const float* gate_b2  = (const float*)d_in[12];
    const float* temp     = (const float*)d_in[13];
    const float* post_w   = (const float*)d_in[14];
    const float* post_b   = (const float*)d_in[15];
    float* out = (float*)d_out;

    cudaFuncSetAttribute((const void*)k_gemm_red,
                         cudaFuncAttributeMaxDynamicSharedMemorySize, GEMM_SMEM);
    cudaFuncSetAttribute((const void*)k_gemm_pipe,
                         cudaFuncAttributeMaxDynamicSharedMemorySize, GEMM_SMEM);

    __nv_bfloat16 *p_fbf, *p_wred, *p_wpost;
    cudaGetSymbolAddress((void**)&p_fbf,   g_fused_bf);
    cudaGetSymbolAddress((void**)&p_wred,  g_wred);
    cudaGetSymbolAddress((void**)&p_wpost, g_wpost);
    __half* p_buf1h;
    cudaGetSymbolAddress((void**)&p_buf1h, g_buf1h);

    cudaStream_t s2;
    cudaStreamCreateWithFlags(&s2, cudaStreamNonBlocking);
    cudaEvent_t e0, e1, e2;
    cudaEventCreateWithFlags(&e0, cudaEventDisableTiming);
    cudaEventCreateWithFlags(&e1, cudaEventDisableTiming);
    cudaEventCreateWithFlags(&e2, cudaEventDisableTiming);

    // fork side stream at entry
    cudaEventRecord(e0, 0);
    cudaStreamWaitEvent(s2, e0, 0);

    // side: post-weight conversion (only needed by gemm_pipe)
    k_cvt<<<(INDIM*2*MIDC/4 + 255)/256, 256, 0, s2>>>(post_w, p_wpost, INDIM*2*MIDC);

    // main: reduce-weight conversion -> reduce GEMM (M=128) -> dw
    k_cvt<<<(MIDC*INDIM/4 + 255)/256, 256>>>(reduce_w, p_wred, MIDC*INDIM);
    k_gemm_red<<<dim3(32, 2, BATCH), 256, GEMM_SMEM>>>(
        p_wred, x, reduce_b, p_buf1h, MIDC);
    k_dw<<<BATCH*MIDC, 256>>>(dw_w, dw_b, bn_gamma, bn_beta, bn_mean, bn_var);

    // fork after dw: branch A (gate -> fwm2) on side stream
    cudaEventRecord(e1, 0);
    cudaStreamWaitEvent(s2, e1, 0);
    k_gate<<<BATCH, 256, 0, s2>>>(gate_w1, gate_b1, gate_w2, gate_b2);
    k_fwm2<<<BATCH*MIDC/2, 512, 0, s2>>>();

    // branch B (gram -> mix-with-softmax) on main
    k_gram<<<dim3(8, HEADS, BATCH), 256>>>();
    k_mix<<<dim3(8, HEADS, BATCH), 256>>>(temp);

    // join: post GEMM needs both halves of fused + wpost
    cudaEventRecord(e2, s2);
    cudaStreamWaitEvent(0, e2, 0);
    k_gemm_pipe<<<dim3(32, 4, BATCH), 256, GEMM_SMEM>>>(
        p_wpost, p_fbf, post_b, x, out, INDIM);
}